// round 1
// baseline (speedup 1.0000x reference)
#include <cuda_runtime.h>
#include <cuda_bf16.h>
#include <cstdint>

// ---------------------------------------------------------------------------
// WindowAttention (Swin shifted-window attention), fp32 baseline.
//   B=32, DIM=256, H=W=64, WIN=8, SHIFT=4, HEADS=8, HEAD_DIM=32, N=64
//   windows: 2048 (=B*64), tokens/window: 64
// Pipeline:
//   K0 gather : x (B,C,H,W) --roll+window-partition--> winxT [C=256][M=131072]
//   K1 gemm   : qkv[M][768] = winxT^T @ qkv_w + qkv_b, scattered to
//               g_qkv[which][win][head][tok][d]
//   K2 attn   : per (win,head): S = scale*QK^T + bias + mask; softmax; O = P V;
//               scatter to out (B,C,H,W) with window-reverse + roll
// ---------------------------------------------------------------------------

#define NWIN_TOT   2048        // B * 64 windows
#define M_TOT      131072      // NWIN_TOT * 64 tokens
#define C_DIM      256
#define N3C        768
#define HEADS      8
#define HD         32
#define NTOK       64
#define SCALE      0.17677669529663687f   // 32^-0.5

// Scratch (static device globals; no allocation at runtime)
__device__ float g_winxT[(size_t)C_DIM * M_TOT];            // 134 MB
__device__ float g_qkv[(size_t)3 * NWIN_TOT * HEADS * NTOK * HD]; // 402 MB

#define QKV_STRIDE ((size_t)NWIN_TOT * HEADS * NTOK * HD)   // 33554432

// ---------------------------------------------------------------------------
// K0: gather with roll(-4,-4) + window partition, write A^T layout
// grid = B*C = 8192 blocks, 256 threads
// ---------------------------------------------------------------------------
__global__ void gather_kernel(const float* __restrict__ x)
{
    int bc = blockIdx.x;              // b*256 + c
    int b  = bc >> 8;
    int c  = bc & 255;
    const float* src = x + ((size_t)bc << 12);                 // plane of 4096
    float* dst = g_winxT + (size_t)c * M_TOT + ((size_t)b << 12);

#pragma unroll
    for (int it = 0; it < 16; ++it) {
        int idx = it * 256 + threadIdx.x;        // 0..4095, coalesced read
        int gh = idx >> 6, gw = idx & 63;
        int hp = (gh + 60) & 63;                 // (gh - SHIFT) mod 64
        int wp = (gw + 60) & 63;
        int wy = hp >> 3, i = hp & 7;
        int wx = wp >> 3, j = wp & 7;
        int m  = (((wy << 3) + wx) << 6) + (i << 3) + j;  // local token index
        dst[m] = src[idx];
    }
}

// ---------------------------------------------------------------------------
// K1: QKV GEMM, 128x128 tile, BK=16, 256 threads, 8x8 register tile
// grid = (1024, 6)
// ---------------------------------------------------------------------------
#define BM 128
#define BN 128
#define BK 16

__global__ void __launch_bounds__(256, 2)
qkv_gemm_kernel(const float* __restrict__ W,     // qkv_w [256][768]
                const float* __restrict__ bias)  // qkv_b [768]
{
    __shared__ __align__(16) float As[BK][BM];
    __shared__ __align__(16) float Bs[BK][BN];

    const int m0  = blockIdx.x * BM;
    const int n0  = blockIdx.y * BN;
    const int tid = threadIdx.x;
    const int lane = tid & 31;
    const int r    = tid >> 5;     // 0..7
    const int ty   = tid >> 4;     // 0..15 (rows)
    const int tx   = tid & 15;     // 0..15 (cols)

    float acc[8][8];
#pragma unroll
    for (int i = 0; i < 8; ++i)
#pragma unroll
        for (int j = 0; j < 8; ++j) acc[i][j] = 0.f;

    float bn[8];
#pragma unroll
    for (int jj = 0; jj < 8; ++jj) bn[jj] = bias[n0 + tx * 8 + jj];

    for (int k0 = 0; k0 < C_DIM; k0 += BK) {
#pragma unroll
        for (int p = 0; p < 2; ++p) {
            int kr = r + p * 8;
            const float4 va = *(const float4*)(g_winxT + (size_t)(k0 + kr) * M_TOT + m0 + lane * 4);
            *(float4*)(&As[kr][lane * 4]) = va;
            const float4 vb = *(const float4*)(W + (size_t)(k0 + kr) * N3C + n0 + lane * 4);
            *(float4*)(&Bs[kr][lane * 4]) = vb;
        }
        __syncthreads();

#pragma unroll
        for (int kk = 0; kk < BK; ++kk) {
            float a[8], bq[8];
            *(float4*)(a)     = *(const float4*)(&As[kk][ty * 8]);
            *(float4*)(a + 4) = *(const float4*)(&As[kk][ty * 8 + 4]);
            *(float4*)(bq)     = *(const float4*)(&Bs[kk][tx * 8]);
            *(float4*)(bq + 4) = *(const float4*)(&Bs[kk][tx * 8 + 4]);
#pragma unroll
            for (int ii = 0; ii < 8; ++ii)
#pragma unroll
                for (int jj = 0; jj < 8; ++jj)
                    acc[ii][jj] += a[ii] * bq[jj];
        }
        __syncthreads();
    }

    // Epilogue: add bias, scatter to g_qkv[which][win][head][tok][d]
#pragma unroll
    for (int ii = 0; ii < 8; ++ii) {
        int m   = m0 + ty * 8 + ii;
        int win = m >> 6;
        int t   = m & 63;
#pragma unroll
        for (int jj = 0; jj < 8; jj += 4) {
            int n     = n0 + tx * 8 + jj;
            int which = n >> 8;
            int head  = (n >> 5) & 7;
            int d     = n & 31;
            float4 v;
            v.x = acc[ii][jj + 0] + bn[jj + 0];
            v.y = acc[ii][jj + 1] + bn[jj + 1];
            v.z = acc[ii][jj + 2] + bn[jj + 2];
            v.w = acc[ii][jj + 3] + bn[jj + 3];
            size_t off = (size_t)which * QKV_STRIDE
                       + ((((size_t)win * HEADS + head) * NTOK + t) * HD + d);
            *(float4*)(g_qkv + off) = v;
        }
    }
}

// ---------------------------------------------------------------------------
// K2: attention per (window, head). grid = (2048, 8), 128 threads
// ---------------------------------------------------------------------------
__global__ void __launch_bounds__(128)
attn_kernel(const float* __restrict__ table,   // rel_bias_table [225][8]
            float* __restrict__ out)           // (B, 256, 64, 64)
{
    const int win  = blockIdx.x;
    const int head = blockIdx.y;
    const int b  = win >> 6;
    const int wy = (win >> 3) & 7;
    const int wx = win & 7;

    __shared__ __align__(16) float QsT[32 * 68];   // [kk][t], also reused as Os
    __shared__ __align__(16) float KsT[32 * 68];   // [kk][s]
    __shared__ __align__(16) float Vs [64 * 36];   // [s][d]
    __shared__ __align__(16) float ST [64 * 68];   // [s][t]
    __shared__ float biasS[225];
    __shared__ int   regS[64];

    const int tid = threadIdx.x;

    const float* qb = g_qkv + (((size_t)win * HEADS + head) << 11);  // *2048
    const float* kb = qb + QKV_STRIDE;
    const float* vb = qb + 2 * QKV_STRIDE;

    // load q,k transposed into smem; v natural
#pragma unroll
    for (int it = 0; it < 16; ++it) {
        int idx = it * 128 + tid;       // 0..2047
        int t = idx >> 5, d = idx & 31;
        QsT[d * 68 + t] = qb[idx];
        KsT[d * 68 + t] = kb[idx];
        Vs [t * 36 + d] = vb[idx];
    }
    for (int i = tid; i < 225; i += 128) biasS[i] = table[i * 8 + head];
    if (tid < 64) {
        int yi = tid >> 3, xi = tid & 7;
        int h = wy * 8 + yi, w = wx * 8 + xi;      // UNSHIFTED mask coords
        int rh = (h < 56) ? 0 : ((h < 60) ? 1 : 2);
        int rw = (w < 56) ? 0 : ((w < 60) ? 1 : 2);
        regS[tid] = rh * 3 + rw;
    }
    __syncthreads();

    const int ty = tid >> 3;   // 0..15
    const int tx = tid & 7;    // 0..7

    // ---- S = scale * Q K^T + bias + mask ----
    {
        float acc[4][8];
#pragma unroll
        for (int i = 0; i < 4; ++i)
#pragma unroll
            for (int j = 0; j < 8; ++j) acc[i][j] = 0.f;

#pragma unroll
        for (int kk = 0; kk < 32; ++kk) {
            float a[4], bq[8];
            *(float4*)a        = *(const float4*)(&QsT[kk * 68 + ty * 4]);
            *(float4*)(bq)     = *(const float4*)(&KsT[kk * 68 + tx * 8]);
            *(float4*)(bq + 4) = *(const float4*)(&KsT[kk * 68 + tx * 8 + 4]);
#pragma unroll
            for (int ii = 0; ii < 4; ++ii)
#pragma unroll
                for (int jj = 0; jj < 8; ++jj)
                    acc[ii][jj] += a[ii] * bq[jj];
        }

#pragma unroll
        for (int ii = 0; ii < 4; ++ii) {
            int t  = ty * 4 + ii;
            int yi = t >> 3, xi = t & 7;
            int rt = regS[t];
#pragma unroll
            for (int jj = 0; jj < 8; ++jj) {
                int s  = tx * 8 + jj;
                int ys = s >> 3, xs = s & 7;
                int bidx = (yi - ys + 7) * 15 + (xi - xs + 7);
                float v = acc[ii][jj] * SCALE + biasS[bidx];
                if (regS[s] != rt) v -= 100.0f;
                ST[s * 68 + t] = v;
            }
        }
    }
    __syncthreads();

    // ---- softmax over s (per token t) ----
    if (tid < 64) {
        int t = tid;
        float mx = -1e30f;
#pragma unroll 8
        for (int s = 0; s < 64; ++s) mx = fmaxf(mx, ST[s * 68 + t]);
        float sum = 0.f;
#pragma unroll 8
        for (int s = 0; s < 64; ++s) {
            float e = __expf(ST[s * 68 + t] - mx);
            ST[s * 68 + t] = e;
            sum += e;
        }
        float inv = 1.0f / sum;
#pragma unroll 8
        for (int s = 0; s < 64; ++s) ST[s * 68 + t] *= inv;
    }
    __syncthreads();

    // ---- O = P V : 64x32, thread tile 4(t) x 4(d) ----
    float o[4][4];
#pragma unroll
    for (int i = 0; i < 4; ++i)
#pragma unroll
        for (int j = 0; j < 4; ++j) o[i][j] = 0.f;

#pragma unroll
    for (int s = 0; s < 64; ++s) {
        float p[4], vv[4];
        *(float4*)p  = *(const float4*)(&ST[s * 68 + ty * 4]);
        *(float4*)vv = *(const float4*)(&Vs[s * 36 + tx * 4]);
#pragma unroll
        for (int ii = 0; ii < 4; ++ii)
#pragma unroll
            for (int jj = 0; jj < 4; ++jj)
                o[ii][jj] += p[ii] * vv[jj];
    }

    // stage into smem (reuse QsT) then coalesced-ish scatter
    float* Os = QsT;                      // needs 64*33 = 2112 <= 2176 floats
    __syncthreads();
#pragma unroll
    for (int ii = 0; ii < 4; ++ii)
#pragma unroll
        for (int jj = 0; jj < 4; ++jj)
            Os[(ty * 4 + ii) * 33 + tx * 4 + jj] = o[ii][jj];
    __syncthreads();

    size_t obase = ((size_t)b << 20) + ((size_t)head << 17);
#pragma unroll
    for (int it = 0; it < 16; ++it) {
        int idx = it * 128 + tid;        // 0..2047
        int d = idx >> 6, t = idx & 63;
        int yi = t >> 3, xi = t & 7;
        int gh = (wy * 8 + yi + 4) & 63;  // roll back +SHIFT
        int gw = (wx * 8 + xi + 4) & 63;
        out[obase + ((size_t)d << 12) + gh * 64 + gw] = Os[t * 33 + d];
    }
}

// ---------------------------------------------------------------------------
extern "C" void kernel_launch(void* const* d_in, const int* in_sizes, int n_in,
                              void* d_out, int out_size)
{
    (void)in_sizes; (void)n_in; (void)out_size;
    const float* x    = (const float*)d_in[0];   // (32,256,64,64)
    const float* qkvw = (const float*)d_in[1];   // (256,768)
    const float* qkvb = (const float*)d_in[2];   // (768,)
    const float* tbl  = (const float*)d_in[3];   // (225,8)
    float* out = (float*)d_out;

    gather_kernel<<<32 * 256, 256>>>(x);
    qkv_gemm_kernel<<<dim3(M_TOT / BM, N3C / BN), 256>>>(qkvw, qkvb);
    attn_kernel<<<dim3(NWIN_TOT, HEADS), 128>>>(tbl, out);
}

// round 4
// speedup vs baseline: 1.6369x; 1.6369x over previous
#include <cuda_runtime.h>
#include <cuda_bf16.h>
#include <cstdint>

// ---------------------------------------------------------------------------
// WindowAttention (Swin shifted-window attention).
//   B=32, DIM=256, H=W=64, WIN=8, SHIFT=4, HEADS=8, HEAD_DIM=32, N=64
// R4: fix gather smem overflow (chunked transpose). QKV GEMM via
//     mma.sync.m16n8k16 bf16 split precision: D = Ah*Bh + Ah*Bl + Al*Bh.
// ---------------------------------------------------------------------------

#define NWIN_TOT   2048
#define M_TOT      131072
#define C_DIM      256
#define N3C        768
#define HEADS      8
#define HD         32
#define NTOK       64
#define SCALE      0.17677669529663687f

__device__ __nv_bfloat16 g_Ahi[(size_t)M_TOT * C_DIM];
__device__ __nv_bfloat16 g_Alo[(size_t)M_TOT * C_DIM];
__device__ __nv_bfloat16 g_Bhi[(size_t)N3C * C_DIM];
__device__ __nv_bfloat16 g_Blo[(size_t)N3C * C_DIM];
__device__ float g_qkv[(size_t)3 * NWIN_TOT * HEADS * NTOK * HD];

#define QKV_STRIDE ((size_t)NWIN_TOT * HEADS * NTOK * HD)

// ------------------------------ helpers -----------------------------------
__device__ __forceinline__ uint32_t smem_u32(const void* p) {
    uint32_t a;
    asm("{ .reg .u64 t; cvta.to.shared.u64 t, %1; cvt.u32.u64 %0, t; }"
        : "=r"(a) : "l"(p));
    return a;
}

__device__ __forceinline__ void cp16(uint32_t saddr, const void* g) {
    asm volatile("cp.async.cg.shared.global [%0], [%1], 16;" :: "r"(saddr), "l"(g));
}
#define CP_COMMIT()  asm volatile("cp.async.commit_group;" ::: "memory")
#define CP_WAIT(N)   asm volatile("cp.async.wait_group %0;" :: "n"(N) : "memory")

#define LDSM_X4(r, addr) \
    asm volatile("ldmatrix.sync.aligned.m8n8.x4.shared.b16 {%0,%1,%2,%3}, [%4];" \
        : "=r"((r)[0]), "=r"((r)[1]), "=r"((r)[2]), "=r"((r)[3]) : "r"(addr))
#define LDSM_X2(r, addr) \
    asm volatile("ldmatrix.sync.aligned.m8n8.x2.shared.b16 {%0,%1}, [%2];" \
        : "=r"((r)[0]), "=r"((r)[1]) : "r"(addr))

#define MMA_BF16(d, a, b) \
    asm volatile("mma.sync.aligned.m16n8k16.row.col.f32.bf16.bf16.f32 " \
        "{%0,%1,%2,%3}, {%4,%5,%6,%7}, {%8,%9}, {%0,%1,%2,%3};" \
        : "+f"((d)[0]), "+f"((d)[1]), "+f"((d)[2]), "+f"((d)[3]) \
        : "r"((a)[0]), "r"((a)[1]), "r"((a)[2]), "r"((a)[3]), \
          "r"((b)[0]), "r"((b)[1]))

__device__ __forceinline__ void split_pack(float v0, float v1, float v2, float v3,
                                           uint2& ph, uint2& pl)
{
    __nv_bfloat16 h0 = __float2bfloat16(v0);
    __nv_bfloat16 h1 = __float2bfloat16(v1);
    __nv_bfloat16 h2 = __float2bfloat16(v2);
    __nv_bfloat16 h3 = __float2bfloat16(v3);
    __nv_bfloat16 l0 = __float2bfloat16(v0 - __bfloat162float(h0));
    __nv_bfloat16 l1 = __float2bfloat16(v1 - __bfloat162float(h1));
    __nv_bfloat16 l2 = __float2bfloat16(v2 - __bfloat162float(h2));
    __nv_bfloat16 l3 = __float2bfloat16(v3 - __bfloat162float(h3));
    ph.x = ((uint32_t)__bfloat16_as_ushort(h1) << 16) | __bfloat16_as_ushort(h0);
    ph.y = ((uint32_t)__bfloat16_as_ushort(h3) << 16) | __bfloat16_as_ushort(h2);
    pl.x = ((uint32_t)__bfloat16_as_ushort(l1) << 16) | __bfloat16_as_ushort(l0);
    pl.y = ((uint32_t)__bfloat16_as_ushort(l3) << 16) | __bfloat16_as_ushort(l2);
}

// ---------------------------------------------------------------------------
// K0: gather + roll + window partition + fp32->bf16 hi/lo split
// grid = 2048 (b,win), 256 threads; 4 chunks of 64 channels via smem transpose
// ---------------------------------------------------------------------------
__global__ void __launch_bounds__(256)
gather_split_kernel(const float* __restrict__ x)
{
    __shared__ float sm[64 * 65];      // [token][channel-in-chunk], pad 65
    const int blk = blockIdx.x;
    const int b  = blk >> 6;
    const int wy = (blk >> 3) & 7;
    const int wx = blk & 7;
    const int tid = threadIdx.x;

    uint2* dh = (uint2*)g_Ahi + (size_t)blk * 4096;   // 64 tok * 64 uint2
    uint2* dl = (uint2*)g_Alo + (size_t)blk * 4096;
    const float* xb = x + ((size_t)b << 20);

#pragma unroll 1
    for (int cc = 0; cc < 4; ++cc) {
        // ---- load 64 channels x 64 tokens, transposing into smem ----
#pragma unroll
        for (int it = 0; it < 16; ++it) {
            int idx = it * 256 + tid;         // 0..4095
            int cl = idx >> 6;                // channel within chunk
            int t  = idx & 63;                // token
            int i = t >> 3, j = t & 7;
            int gh = (wy * 8 + i + 4) & 63;
            int gw = (wx * 8 + j + 4) & 63;
            sm[t * 65 + cl] = xb[((size_t)(cc * 64 + cl) << 12) + gh * 64 + gw];
        }
        __syncthreads();
        // ---- convert + pack + coalesced store ----
#pragma unroll
        for (int it = 0; it < 4; ++it) {
            int idx = it * 256 + tid;         // 0..1023
            int t  = idx >> 4;                // token
            int cq = idx & 15;                // 4-channel group within chunk
            const float* s = sm + t * 65 + cq * 4;
            uint2 ph, pl;
            split_pack(s[0], s[1], s[2], s[3], ph, pl);
            dh[t * 64 + cc * 16 + cq] = ph;
            dl[t * 64 + cc * 16 + cq] = pl;
        }
        __syncthreads();
    }
}

// ---------------------------------------------------------------------------
// K0b: transpose qkv_w [K=256][N=768] -> B [N][K] bf16 hi/lo
// ---------------------------------------------------------------------------
__global__ void __launch_bounds__(256)
transW_kernel(const float* __restrict__ W)
{
    int g = blockIdx.x * 256 + threadIdx.x;   // 0..49151
    int n = g >> 6;
    int k4 = (g & 63) * 4;
    float v[4];
#pragma unroll
    for (int r = 0; r < 4; ++r) v[r] = W[(size_t)(k4 + r) * N3C + n];
    uint2 ph, pl;
    split_pack(v[0], v[1], v[2], v[3], ph, pl);
    ((uint2*)g_Bhi)[(size_t)n * 64 + (k4 >> 2)] = ph;
    ((uint2*)g_Blo)[(size_t)n * 64 + (k4 >> 2)] = pl;
}

// ---------------------------------------------------------------------------
// K1: HMMA split-bf16 QKV GEMM. grid = (6, 1024), 256 threads (8 warps 4x2).
// Tile 128(M)x128(N), K=256 in 4 chunks of 64, cp.async double buffer.
// smem per stage: Ah|Al|Bh|Bl, each 128 rows x 72 bf16 (144 B) = 18432 B
// ---------------------------------------------------------------------------
#define ROWB 144
#define ARR  (128 * ROWB)
#define STG  (4 * ARR)

__global__ void __launch_bounds__(256, 1)
qkv_mma_kernel(const float* __restrict__ bias)
{
    extern __shared__ __align__(128) char dsm[];
    const uint32_t su = smem_u32(dsm);

    const int tid  = threadIdx.x;
    const int lane = tid & 31;
    const int wid  = tid >> 5;
    const int wm   = wid >> 1;            // 0..3 (M)
    const int wn   = wid & 1;             // 0..1 (N)
    const int n0   = blockIdx.x * 128;
    const int m0   = blockIdx.y * 128;

    const __nv_bfloat16* pAh = g_Ahi + (size_t)m0 * C_DIM;
    const __nv_bfloat16* pAl = g_Alo + (size_t)m0 * C_DIM;
    const __nv_bfloat16* pBh = g_Bhi + (size_t)n0 * C_DIM;
    const __nv_bfloat16* pBl = g_Blo + (size_t)n0 * C_DIM;

    const int ldRow = tid >> 3;           // 0..31
    const int ldCol = tid & 7;            // 0..7

    const uint32_t aRow = (uint32_t)(wm * 32 + ((lane >> 3) & 1) * 8 + (lane & 7)) * ROWB
                        + (uint32_t)(lane >> 4) * 16;
    const uint32_t bRow = (uint32_t)(wn * 64 + (lane & 7)) * ROWB
                        + (uint32_t)((lane >> 3) & 1) * 16;

    float acc[2][8][4];
#pragma unroll
    for (int i = 0; i < 2; ++i)
#pragma unroll
        for (int j = 0; j < 8; ++j)
#pragma unroll
            for (int q = 0; q < 4; ++q) acc[i][j][q] = 0.f;

    auto load_chunk = [&](int c, int st) {
        const uint32_t sb = su + st * STG;
        const int kb = c * 64 + ldCol * 8;
#pragma unroll
        for (int p = 0; p < 4; ++p) {
            int row = p * 32 + ldRow;
            uint32_t so = (uint32_t)row * ROWB + (uint32_t)ldCol * 16;
            size_t gi = (size_t)row * C_DIM + kb;
            cp16(sb + 0 * ARR + so, pAh + gi);
            cp16(sb + 1 * ARR + so, pAl + gi);
            cp16(sb + 2 * ARR + so, pBh + gi);
            cp16(sb + 3 * ARR + so, pBl + gi);
        }
        CP_COMMIT();
    };

    load_chunk(0, 0);

#pragma unroll 1
    for (int c = 0; c < 4; ++c) {
        if (c < 3) { load_chunk(c + 1, (c + 1) & 1); CP_WAIT(1); }
        else       { CP_WAIT(0); }
        __syncthreads();

        const uint32_t sb  = su + (c & 1) * STG;
        const uint32_t sAh = sb;
        const uint32_t sAl = sb + ARR;
        const uint32_t sBh = sb + 2 * ARR;
        const uint32_t sBl = sb + 3 * ARR;

#pragma unroll
        for (int ks = 0; ks < 4; ++ks) {
            uint32_t ah[2][4], al[2][4];
#pragma unroll
            for (int mt = 0; mt < 2; ++mt) {
                uint32_t ao = aRow + (uint32_t)mt * (16 * ROWB) + (uint32_t)ks * 32;
                LDSM_X4(ah[mt], sAh + ao);
                LDSM_X4(al[mt], sAl + ao);
            }
#pragma unroll
            for (int nt = 0; nt < 8; ++nt) {
                uint32_t bo = bRow + (uint32_t)nt * (8 * ROWB) + (uint32_t)ks * 32;
                uint32_t bh[2], bl[2];
                LDSM_X2(bh, sBh + bo);
                LDSM_X2(bl, sBl + bo);
                MMA_BF16(acc[0][nt], ah[0], bh);
                MMA_BF16(acc[1][nt], ah[1], bh);
                MMA_BF16(acc[0][nt], ah[0], bl);
                MMA_BF16(acc[1][nt], ah[1], bl);
                MMA_BF16(acc[0][nt], al[0], bh);
                MMA_BF16(acc[1][nt], al[1], bh);
            }
        }
        __syncthreads();
    }

    // ---- epilogue: bias add + scatter to g_qkv[which][win][head][t][d] ----
#pragma unroll
    for (int nt = 0; nt < 8; ++nt) {
        const int n = n0 + wn * 64 + nt * 8 + (lane & 3) * 2;
        const float2 bv = *(const float2*)(bias + n);
        const int which = n >> 8;
        const int head  = (n >> 5) & 7;
        const int d     = n & 31;
        const size_t nbase = (size_t)which * QKV_STRIDE + (size_t)head * (NTOK * HD) + d;
#pragma unroll
        for (int mt = 0; mt < 2; ++mt) {
            const int mb = m0 + wm * 32 + mt * 16 + (lane >> 2);
#pragma unroll
            for (int h = 0; h < 2; ++h) {
                const int m   = mb + h * 8;
                const int win = m >> 6;
                const int t   = m & 63;
                float2 v;
                v.x = acc[mt][nt][h * 2 + 0] + bv.x;
                v.y = acc[mt][nt][h * 2 + 1] + bv.y;
                *(float2*)(g_qkv + nbase + ((size_t)win * (HEADS * NTOK * HD) + (size_t)t * HD)) = v;
            }
        }
    }
}

// ---------------------------------------------------------------------------
// K2: attention per (window, head). grid = (2048, 8), 128 threads
// ---------------------------------------------------------------------------
__global__ void __launch_bounds__(128)
attn_kernel(const float* __restrict__ table,
            float* __restrict__ out)
{
    const int win  = blockIdx.x;
    const int head = blockIdx.y;
    const int b  = win >> 6;
    const int wy = (win >> 3) & 7;
    const int wx = win & 7;

    __shared__ __align__(16) float QsT[32 * 68];
    __shared__ __align__(16) float KsT[32 * 68];
    __shared__ __align__(16) float Vs [64 * 36];
    __shared__ __align__(16) float ST [64 * 68];
    __shared__ float biasS[225];
    __shared__ int   regS[64];

    const int tid = threadIdx.x;

    const float* qb = g_qkv + (((size_t)win * HEADS + head) << 11);
    const float* kb = qb + QKV_STRIDE;
    const float* vb = qb + 2 * QKV_STRIDE;

#pragma unroll
    for (int it = 0; it < 16; ++it) {
        int idx = it * 128 + tid;
        int t = idx >> 5, d = idx & 31;
        QsT[d * 68 + t] = qb[idx];
        KsT[d * 68 + t] = kb[idx];
        Vs [t * 36 + d] = vb[idx];
    }
    for (int i = tid; i < 225; i += 128) biasS[i] = table[i * 8 + head];
    if (tid < 64) {
        int yi = tid >> 3, xi = tid & 7;
        int h = wy * 8 + yi, w = wx * 8 + xi;
        int rh = (h < 56) ? 0 : ((h < 60) ? 1 : 2);
        int rw = (w < 56) ? 0 : ((w < 60) ? 1 : 2);
        regS[tid] = rh * 3 + rw;
    }
    __syncthreads();

    const int ty = tid >> 3;
    const int tx = tid & 7;

    {
        float acc[4][8];
#pragma unroll
        for (int i = 0; i < 4; ++i)
#pragma unroll
            for (int j = 0; j < 8; ++j) acc[i][j] = 0.f;

#pragma unroll
        for (int kk = 0; kk < 32; ++kk) {
            float a[4], bq[8];
            *(float4*)a        = *(const float4*)(&QsT[kk * 68 + ty * 4]);
            *(float4*)(bq)     = *(const float4*)(&KsT[kk * 68 + tx * 8]);
            *(float4*)(bq + 4) = *(const float4*)(&KsT[kk * 68 + tx * 8 + 4]);
#pragma unroll
            for (int ii = 0; ii < 4; ++ii)
#pragma unroll
                for (int jj = 0; jj < 8; ++jj)
                    acc[ii][jj] += a[ii] * bq[jj];
        }

#pragma unroll
        for (int ii = 0; ii < 4; ++ii) {
            int t  = ty * 4 + ii;
            int yi = t >> 3, xi = t & 7;
            int rt = regS[t];
#pragma unroll
            for (int jj = 0; jj < 8; ++jj) {
                int s  = tx * 8 + jj;
                int ys = s >> 3, xs = s & 7;
                int bidx = (yi - ys + 7) * 15 + (xi - xs + 7);
                float v = acc[ii][jj] * SCALE + biasS[bidx];
                if (regS[s] != rt) v -= 100.0f;
                ST[s * 68 + t] = v;
            }
        }
    }
    __syncthreads();

    if (tid < 64) {
        int t = tid;
        float mx = -1e30f;
#pragma unroll 8
        for (int s = 0; s < 64; ++s) mx = fmaxf(mx, ST[s * 68 + t]);
        float sum = 0.f;
#pragma unroll 8
        for (int s = 0; s < 64; ++s) {
            float e = __expf(ST[s * 68 + t] - mx);
            ST[s * 68 + t] = e;
            sum += e;
        }
        float inv = 1.0f / sum;
#pragma unroll 8
        for (int s = 0; s < 64; ++s) ST[s * 68 + t] *= inv;
    }
    __syncthreads();

    float o[4][4];
#pragma unroll
    for (int i = 0; i < 4; ++i)
#pragma unroll
        for (int j = 0; j < 4; ++j) o[i][j] = 0.f;

#pragma unroll
    for (int s = 0; s < 64; ++s) {
        float p[4], vv[4];
        *(float4*)p  = *(const float4*)(&ST[s * 68 + ty * 4]);
        *(float4*)vv = *(const float4*)(&Vs[s * 36 + tx * 4]);
#pragma unroll
        for (int ii = 0; ii < 4; ++ii)
#pragma unroll
            for (int jj = 0; jj < 4; ++jj)
                o[ii][jj] += p[ii] * vv[jj];
    }

    float* Os = QsT;
    __syncthreads();
#pragma unroll
    for (int ii = 0; ii < 4; ++ii)
#pragma unroll
        for (int jj = 0; jj < 4; ++jj)
            Os[(ty * 4 + ii) * 33 + tx * 4 + jj] = o[ii][jj];
    __syncthreads();

    size_t obase = ((size_t)b << 20) + ((size_t)head << 17);
#pragma unroll
    for (int it = 0; it < 16; ++it) {
        int idx = it * 128 + tid;
        int d = idx >> 6, t = idx & 63;
        int yi = t >> 3, xi = t & 7;
        int gh = (wy * 8 + yi + 4) & 63;
        int gw = (wx * 8 + xi + 4) & 63;
        out[obase + ((size_t)d << 12) + gh * 64 + gw] = Os[t * 33 + d];
    }
}

// ---------------------------------------------------------------------------
extern "C" void kernel_launch(void* const* d_in, const int* in_sizes, int n_in,
                              void* d_out, int out_size)
{
    (void)in_sizes; (void)n_in; (void)out_size;
    const float* x    = (const float*)d_in[0];
    const float* qkvw = (const float*)d_in[1];
    const float* qkvb = (const float*)d_in[2];
    const float* tbl  = (const float*)d_in[3];
    float* out = (float*)d_out;

    cudaFuncSetAttribute(qkv_mma_kernel,
                         cudaFuncAttributeMaxDynamicSharedMemorySize, 2 * STG);

    gather_split_kernel<<<NWIN_TOT, 256>>>(x);
    transW_kernel<<<192, 256>>>(qkvw);
    qkv_mma_kernel<<<dim3(6, 1024), 256, 2 * STG>>>(qkvb);
    attn_kernel<<<dim3(NWIN_TOT, HEADS), 128>>>(tbl, out);
}

// round 5
// speedup vs baseline: 2.2074x; 1.3485x over previous
#include <cuda_runtime.h>
#include <cuda_bf16.h>
#include <cstdint>

// ---------------------------------------------------------------------------
// WindowAttention (Swin shifted-window attention).
//   B=32, DIM=256, H=W=64, WIN=8, SHIFT=4, HEADS=8, HEAD_DIM=32, N=64
// R5: HMMA attention (register softmax, split-bf16 3-term for S and PV).
//     QKV GEMM via mma.sync.m16n8k16 bf16 split precision (R4, B-ldsm x4).
// ---------------------------------------------------------------------------

#define NWIN_TOT   2048
#define M_TOT      131072
#define C_DIM      256
#define N3C        768
#define HEADS      8
#define HD         32
#define NTOK       64
#define SCALE      0.17677669529663687f

__device__ __nv_bfloat16 g_Ahi[(size_t)M_TOT * C_DIM];
__device__ __nv_bfloat16 g_Alo[(size_t)M_TOT * C_DIM];
__device__ __nv_bfloat16 g_Bhi[(size_t)N3C * C_DIM];
__device__ __nv_bfloat16 g_Blo[(size_t)N3C * C_DIM];
__device__ float g_qkv[(size_t)3 * NWIN_TOT * HEADS * NTOK * HD];

#define QKV_STRIDE ((size_t)NWIN_TOT * HEADS * NTOK * HD)

// ------------------------------ helpers -----------------------------------
__device__ __forceinline__ uint32_t smem_u32(const void* p) {
    uint32_t a;
    asm("{ .reg .u64 t; cvta.to.shared.u64 t, %1; cvt.u32.u64 %0, t; }"
        : "=r"(a) : "l"(p));
    return a;
}

__device__ __forceinline__ void cp16(uint32_t saddr, const void* g) {
    asm volatile("cp.async.cg.shared.global [%0], [%1], 16;" :: "r"(saddr), "l"(g));
}
#define CP_COMMIT()  asm volatile("cp.async.commit_group;" ::: "memory")
#define CP_WAIT(N)   asm volatile("cp.async.wait_group %0;" :: "n"(N) : "memory")

#define LDSM_X4(r, addr) \
    asm volatile("ldmatrix.sync.aligned.m8n8.x4.shared.b16 {%0,%1,%2,%3}, [%4];" \
        : "=r"((r)[0]), "=r"((r)[1]), "=r"((r)[2]), "=r"((r)[3]) : "r"(addr))
#define LDSM_X4T(r, addr) \
    asm volatile("ldmatrix.sync.aligned.m8n8.x4.trans.shared.b16 {%0,%1,%2,%3}, [%4];" \
        : "=r"((r)[0]), "=r"((r)[1]), "=r"((r)[2]), "=r"((r)[3]) : "r"(addr))

#define MMA_BF16(d, a, b) \
    asm volatile("mma.sync.aligned.m16n8k16.row.col.f32.bf16.bf16.f32 " \
        "{%0,%1,%2,%3}, {%4,%5,%6,%7}, {%8,%9}, {%0,%1,%2,%3};" \
        : "+f"((d)[0]), "+f"((d)[1]), "+f"((d)[2]), "+f"((d)[3]) \
        : "r"((a)[0]), "r"((a)[1]), "r"((a)[2]), "r"((a)[3]), \
          "r"((b)[0]), "r"((b)[1]))

__device__ __forceinline__ void split_pack(float v0, float v1, float v2, float v3,
                                           uint2& ph, uint2& pl)
{
    __nv_bfloat16 h0 = __float2bfloat16(v0);
    __nv_bfloat16 h1 = __float2bfloat16(v1);
    __nv_bfloat16 h2 = __float2bfloat16(v2);
    __nv_bfloat16 h3 = __float2bfloat16(v3);
    __nv_bfloat16 l0 = __float2bfloat16(v0 - __bfloat162float(h0));
    __nv_bfloat16 l1 = __float2bfloat16(v1 - __bfloat162float(h1));
    __nv_bfloat16 l2 = __float2bfloat16(v2 - __bfloat162float(h2));
    __nv_bfloat16 l3 = __float2bfloat16(v3 - __bfloat162float(h3));
    ph.x = ((uint32_t)__bfloat16_as_ushort(h1) << 16) | __bfloat16_as_ushort(h0);
    ph.y = ((uint32_t)__bfloat16_as_ushort(h3) << 16) | __bfloat16_as_ushort(h2);
    pl.x = ((uint32_t)__bfloat16_as_ushort(l1) << 16) | __bfloat16_as_ushort(l0);
    pl.y = ((uint32_t)__bfloat16_as_ushort(l3) << 16) | __bfloat16_as_ushort(l2);
}

// pack two floats -> bf16x2 (lo = x, hi = y), plus residual pack
__device__ __forceinline__ void split_pack2(float x, float y, uint32_t& h, uint32_t& l)
{
    __nv_bfloat16 hx = __float2bfloat16(x);
    __nv_bfloat16 hy = __float2bfloat16(y);
    __nv_bfloat16 lx = __float2bfloat16(x - __bfloat162float(hx));
    __nv_bfloat16 ly = __float2bfloat16(y - __bfloat162float(hy));
    h = ((uint32_t)__bfloat16_as_ushort(hy) << 16) | __bfloat16_as_ushort(hx);
    l = ((uint32_t)__bfloat16_as_ushort(ly) << 16) | __bfloat16_as_ushort(lx);
}

// ---------------------------------------------------------------------------
// K0: gather + roll + window partition + fp32->bf16 hi/lo split
// ---------------------------------------------------------------------------
__global__ void __launch_bounds__(256)
gather_split_kernel(const float* __restrict__ x)
{
    __shared__ float sm[64 * 65];
    const int blk = blockIdx.x;
    const int b  = blk >> 6;
    const int wy = (blk >> 3) & 7;
    const int wx = blk & 7;
    const int tid = threadIdx.x;

    uint2* dh = (uint2*)g_Ahi + (size_t)blk * 4096;
    uint2* dl = (uint2*)g_Alo + (size_t)blk * 4096;
    const float* xb = x + ((size_t)b << 20);

#pragma unroll 1
    for (int cc = 0; cc < 4; ++cc) {
#pragma unroll
        for (int it = 0; it < 16; ++it) {
            int idx = it * 256 + tid;
            int cl = idx >> 6;
            int t  = idx & 63;
            int i = t >> 3, j = t & 7;
            int gh = (wy * 8 + i + 4) & 63;
            int gw = (wx * 8 + j + 4) & 63;
            sm[t * 65 + cl] = xb[((size_t)(cc * 64 + cl) << 12) + gh * 64 + gw];
        }
        __syncthreads();
#pragma unroll
        for (int it = 0; it < 4; ++it) {
            int idx = it * 256 + tid;
            int t  = idx >> 4;
            int cq = idx & 15;
            const float* s = sm + t * 65 + cq * 4;
            uint2 ph, pl;
            split_pack(s[0], s[1], s[2], s[3], ph, pl);
            dh[t * 64 + cc * 16 + cq] = ph;
            dl[t * 64 + cc * 16 + cq] = pl;
        }
        __syncthreads();
    }
}

// ---------------------------------------------------------------------------
// K0b: transpose qkv_w [K=256][N=768] -> B [N][K] bf16 hi/lo
// ---------------------------------------------------------------------------
__global__ void __launch_bounds__(256)
transW_kernel(const float* __restrict__ W)
{
    int g = blockIdx.x * 256 + threadIdx.x;
    int n = g >> 6;
    int k4 = (g & 63) * 4;
    float v[4];
#pragma unroll
    for (int r = 0; r < 4; ++r) v[r] = W[(size_t)(k4 + r) * N3C + n];
    uint2 ph, pl;
    split_pack(v[0], v[1], v[2], v[3], ph, pl);
    ((uint2*)g_Bhi)[(size_t)n * 64 + (k4 >> 2)] = ph;
    ((uint2*)g_Blo)[(size_t)n * 64 + (k4 >> 2)] = pl;
}

// ---------------------------------------------------------------------------
// K1: HMMA split-bf16 QKV GEMM. grid = (6, 1024), 256 threads (8 warps 4x2).
// ---------------------------------------------------------------------------
#define ROWB 144
#define ARR  (128 * ROWB)
#define STG  (4 * ARR)

__global__ void __launch_bounds__(256, 1)
qkv_mma_kernel(const float* __restrict__ bias)
{
    extern __shared__ __align__(128) char dsm[];
    const uint32_t su = smem_u32(dsm);

    const int tid  = threadIdx.x;
    const int lane = tid & 31;
    const int wid  = tid >> 5;
    const int wm   = wid >> 1;
    const int wn   = wid & 1;
    const int n0   = blockIdx.x * 128;
    const int m0   = blockIdx.y * 128;

    const __nv_bfloat16* pAh = g_Ahi + (size_t)m0 * C_DIM;
    const __nv_bfloat16* pAl = g_Alo + (size_t)m0 * C_DIM;
    const __nv_bfloat16* pBh = g_Bhi + (size_t)n0 * C_DIM;
    const __nv_bfloat16* pBl = g_Blo + (size_t)n0 * C_DIM;

    const int ldRow = tid >> 3;
    const int ldCol = tid & 7;

    const uint32_t aRow = (uint32_t)(wm * 32 + ((lane >> 3) & 1) * 8 + (lane & 7)) * ROWB
                        + (uint32_t)(lane >> 4) * 16;
    // x4 B addressing: 2 consecutive n8-tiles per load
    const uint32_t bRow = (uint32_t)(wn * 64 + ((lane >> 4) << 3) + (lane & 7)) * ROWB
                        + (uint32_t)((lane >> 3) & 1) * 16;

    float acc[2][8][4];
#pragma unroll
    for (int i = 0; i < 2; ++i)
#pragma unroll
        for (int j = 0; j < 8; ++j)
#pragma unroll
            for (int q = 0; q < 4; ++q) acc[i][j][q] = 0.f;

    auto load_chunk = [&](int c, int st) {
        const uint32_t sb = su + st * STG;
        const int kb = c * 64 + ldCol * 8;
#pragma unroll
        for (int p = 0; p < 4; ++p) {
            int row = p * 32 + ldRow;
            uint32_t so = (uint32_t)row * ROWB + (uint32_t)ldCol * 16;
            size_t gi = (size_t)row * C_DIM + kb;
            cp16(sb + 0 * ARR + so, pAh + gi);
            cp16(sb + 1 * ARR + so, pAl + gi);
            cp16(sb + 2 * ARR + so, pBh + gi);
            cp16(sb + 3 * ARR + so, pBl + gi);
        }
        CP_COMMIT();
    };

    load_chunk(0, 0);

#pragma unroll 1
    for (int c = 0; c < 4; ++c) {
        if (c < 3) { load_chunk(c + 1, (c + 1) & 1); CP_WAIT(1); }
        else       { CP_WAIT(0); }
        __syncthreads();

        const uint32_t sb  = su + (c & 1) * STG;
        const uint32_t sAh = sb;
        const uint32_t sAl = sb + ARR;
        const uint32_t sBh = sb + 2 * ARR;
        const uint32_t sBl = sb + 3 * ARR;

#pragma unroll
        for (int ks = 0; ks < 4; ++ks) {
            uint32_t ah[2][4], al[2][4];
#pragma unroll
            for (int mt = 0; mt < 2; ++mt) {
                uint32_t ao = aRow + (uint32_t)mt * (16 * ROWB) + (uint32_t)ks * 32;
                LDSM_X4(ah[mt], sAh + ao);
                LDSM_X4(al[mt], sAl + ao);
            }
#pragma unroll
            for (int np = 0; np < 4; ++np) {
                uint32_t bo = bRow + (uint32_t)np * (16 * ROWB) + (uint32_t)ks * 32;
                uint32_t bh[4], bl[4];
                LDSM_X4(bh, sBh + bo);
                LDSM_X4(bl, sBl + bo);
#pragma unroll
                for (int half = 0; half < 2; ++half) {
                    int nt = np * 2 + half;
                    MMA_BF16(acc[0][nt], ah[0], bh + half * 2);
                    MMA_BF16(acc[1][nt], ah[1], bh + half * 2);
                    MMA_BF16(acc[0][nt], ah[0], bl + half * 2);
                    MMA_BF16(acc[1][nt], ah[1], bl + half * 2);
                    MMA_BF16(acc[0][nt], al[0], bh + half * 2);
                    MMA_BF16(acc[1][nt], al[1], bh + half * 2);
                }
            }
        }
        __syncthreads();
    }

#pragma unroll
    for (int nt = 0; nt < 8; ++nt) {
        const int n = n0 + wn * 64 + nt * 8 + (lane & 3) * 2;
        const float2 bv = *(const float2*)(bias + n);
        const int which = n >> 8;
        const int head  = (n >> 5) & 7;
        const int d     = n & 31;
        const size_t nbase = (size_t)which * QKV_STRIDE + (size_t)head * (NTOK * HD) + d;
#pragma unroll
        for (int mt = 0; mt < 2; ++mt) {
            const int mb = m0 + wm * 32 + mt * 16 + (lane >> 2);
#pragma unroll
            for (int h = 0; h < 2; ++h) {
                const int m   = mb + h * 8;
                const int win = m >> 6;
                const int t   = m & 63;
                float2 v;
                v.x = acc[mt][nt][h * 2 + 0] + bv.x;
                v.y = acc[mt][nt][h * 2 + 1] + bv.y;
                *(float2*)(g_qkv + nbase + ((size_t)win * (HEADS * NTOK * HD) + (size_t)t * HD)) = v;
            }
        }
    }
}

// ---------------------------------------------------------------------------
// K2: HMMA attention. grid = (2048, 8), 128 threads (4 warps, 16 rows each).
// Q/K/V split hi/lo bf16 in smem; S and P live in MMA fragments; register
// softmax via butterfly shuffles; 3-term split MMA for both S and PV.
// ---------------------------------------------------------------------------
#define ASTRIDE 80                 // bytes per 32-elem bf16 row (40 bf16)
#define AQH 0
#define AQL 5120
#define AKH 10240
#define AKL 15360
#define AVH 20480
#define AVL 25600

__global__ void __launch_bounds__(128)
attn_kernel(const float* __restrict__ table,
            float* __restrict__ out)
{
    __shared__ __align__(16) char smr[30720];
    __shared__ float biasS[225];
    __shared__ int   regS[64];

    const int win  = blockIdx.x;
    const int head = blockIdx.y;
    const int b  = win >> 6;
    const int wy = (win >> 3) & 7;
    const int wx = win & 7;

    const int tid  = threadIdx.x;
    const int lane = tid & 31;
    const int wid  = tid >> 5;
    const uint32_t sb = smem_u32(smr);

    const float* qb = g_qkv + (((size_t)win * HEADS + head) << 11);
    const float* kb = qb + QKV_STRIDE;
    const float* vb = qb + 2 * QKV_STRIDE;

    // ---- load + split into smem: [t][d] bf16, row stride 80B ----
    {
        auto load_split = [&](const float* src, int off, float scale) {
#pragma unroll
            for (int it = 0; it < 8; ++it) {
                int idx2 = it * 128 + tid;          // 0..1023 float2 units
                int t  = idx2 >> 4;
                int dp = idx2 & 15;                  // d = 2*dp
                float2 v = ((const float2*)src)[idx2];
                uint32_t h, l;
                split_pack2(v.x * scale, v.y * scale, h, l);
                *(uint32_t*)(smr + off + t * ASTRIDE + dp * 4) = h;
                *(uint32_t*)(smr + off + 5120 + t * ASTRIDE + dp * 4) = l;
            }
        };
        load_split(qb, AQH, SCALE);
        load_split(kb, AKH, 1.0f);
        load_split(vb, AVH, 1.0f);
    }
    for (int i = tid; i < 225; i += 128) biasS[i] = table[i * 8 + head];
    if (tid < 64) {
        int yi = tid >> 3, xi = tid & 7;
        int h = wy * 8 + yi, w = wx * 8 + xi;
        int rh = (h < 56) ? 0 : ((h < 60) ? 1 : 2);
        int rw = (w < 56) ? 0 : ((w < 60) ? 1 : 2);
        regS[tid] = rh * 3 + rw;
    }
    __syncthreads();

    const int m0 = wid * 16;

    // ---- S = (Q*SCALE) K^T via 3-term split MMA ----
    float accS[8][4];
#pragma unroll
    for (int i = 0; i < 8; ++i)
#pragma unroll
        for (int q = 0; q < 4; ++q) accS[i][q] = 0.f;

    const uint32_t aoff = (uint32_t)(m0 + (lane & 15)) * ASTRIDE + (uint32_t)(lane >> 4) * 16;
    const uint32_t koff = (uint32_t)(((lane >> 4) << 3) + (lane & 7)) * ASTRIDE
                        + (uint32_t)((lane >> 3) & 1) * 16;

#pragma unroll
    for (int kt = 0; kt < 2; ++kt) {
        uint32_t qh[4], ql[4];
        LDSM_X4(qh, sb + AQH + aoff + kt * 32);
        LDSM_X4(ql, sb + AQL + aoff + kt * 32);
#pragma unroll
        for (int np = 0; np < 4; ++np) {
            uint32_t kh[4], kl[4];
            uint32_t bo = koff + (uint32_t)np * (16 * ASTRIDE) + kt * 32;
            LDSM_X4(kh, sb + AKH + bo);
            LDSM_X4(kl, sb + AKL + bo);
#pragma unroll
            for (int half = 0; half < 2; ++half) {
                int nt = np * 2 + half;
                MMA_BF16(accS[nt], qh, kh + half * 2);
                MMA_BF16(accS[nt], qh, kl + half * 2);
                MMA_BF16(accS[nt], ql, kh + half * 2);
            }
        }
    }

    // ---- bias + mask (registers) ----
    const int r0 = m0 + (lane >> 2);
    const int r1 = r0 + 8;
    const int yi0 = r0 >> 3, xi0 = r0 & 7, rg0 = regS[r0];
    const int yi1 = r1 >> 3, xi1 = r1 & 7, rg1 = regS[r1];
#pragma unroll
    for (int nt = 0; nt < 8; ++nt) {
#pragma unroll
        for (int e = 0; e < 2; ++e) {
            int s  = nt * 8 + (lane & 3) * 2 + e;
            int ys = s >> 3, xs = s & 7;
            int rs = regS[s];
            accS[nt][e]     += biasS[(yi0 - ys + 7) * 15 + (xi0 - xs + 7)]
                             + (rs != rg0 ? -100.0f : 0.0f);
            accS[nt][2 + e] += biasS[(yi1 - ys + 7) * 15 + (xi1 - xs + 7)]
                             + (rs != rg1 ? -100.0f : 0.0f);
        }
    }

    // ---- register softmax: rows live in 4 lanes (lane&3) ----
    {
        float mx0 = -1e30f, mx1 = -1e30f;
#pragma unroll
        for (int nt = 0; nt < 8; ++nt) {
            mx0 = fmaxf(mx0, fmaxf(accS[nt][0], accS[nt][1]));
            mx1 = fmaxf(mx1, fmaxf(accS[nt][2], accS[nt][3]));
        }
#pragma unroll
        for (int o = 1; o < 4; o <<= 1) {
            mx0 = fmaxf(mx0, __shfl_xor_sync(0xFFFFFFFF, mx0, o));
            mx1 = fmaxf(mx1, __shfl_xor_sync(0xFFFFFFFF, mx1, o));
        }
        float sum0 = 0.f, sum1 = 0.f;
#pragma unroll
        for (int nt = 0; nt < 8; ++nt) {
            accS[nt][0] = __expf(accS[nt][0] - mx0);
            accS[nt][1] = __expf(accS[nt][1] - mx0);
            accS[nt][2] = __expf(accS[nt][2] - mx1);
            accS[nt][3] = __expf(accS[nt][3] - mx1);
            sum0 += accS[nt][0] + accS[nt][1];
            sum1 += accS[nt][2] + accS[nt][3];
        }
#pragma unroll
        for (int o = 1; o < 4; o <<= 1) {
            sum0 += __shfl_xor_sync(0xFFFFFFFF, sum0, o);
            sum1 += __shfl_xor_sync(0xFFFFFFFF, sum1, o);
        }
        float inv0 = 1.0f / sum0, inv1 = 1.0f / sum1;
#pragma unroll
        for (int nt = 0; nt < 8; ++nt) {
            accS[nt][0] *= inv0; accS[nt][1] *= inv0;
            accS[nt][2] *= inv1; accS[nt][3] *= inv1;
        }
    }

    // ---- pack P into A-fragments (hi/lo) ----
    uint32_t ph[4][4], pl[4][4];
#pragma unroll
    for (int kt = 0; kt < 4; ++kt) {
        split_pack2(accS[2 * kt][0],     accS[2 * kt][1],     ph[kt][0], pl[kt][0]);
        split_pack2(accS[2 * kt][2],     accS[2 * kt][3],     ph[kt][1], pl[kt][1]);
        split_pack2(accS[2 * kt + 1][0], accS[2 * kt + 1][1], ph[kt][2], pl[kt][2]);
        split_pack2(accS[2 * kt + 1][2], accS[2 * kt + 1][3], ph[kt][3], pl[kt][3]);
    }

    // ---- O = P V via 3-term split MMA (V via ldmatrix.trans) ----
    float accO[4][4];
#pragma unroll
    for (int i = 0; i < 4; ++i)
#pragma unroll
        for (int q = 0; q < 4; ++q) accO[i][q] = 0.f;

    const uint32_t vrow = (uint32_t)((lane & 7) + ((lane >> 3) & 1) * 8) * ASTRIDE
                        + (uint32_t)((lane >> 4) << 3) * 2;
#pragma unroll
    for (int kt = 0; kt < 4; ++kt) {
#pragma unroll
        for (int np = 0; np < 2; ++np) {
            uint32_t vh[4], vl[4];
            uint32_t vo = vrow + (uint32_t)kt * (16 * ASTRIDE) + (uint32_t)np * 32;
            LDSM_X4T(vh, sb + AVH + vo);
            LDSM_X4T(vl, sb + AVL + vo);
#pragma unroll
            for (int half = 0; half < 2; ++half) {
                int nt = np * 2 + half;
                MMA_BF16(accO[nt], ph[kt], vh + half * 2);
                MMA_BF16(accO[nt], ph[kt], vl + half * 2);
                MMA_BF16(accO[nt], pl[kt], vh + half * 2);
            }
        }
    }

    // ---- stage O in smem (overlay Q region), then coalesced scatter ----
    __syncthreads();
    float* Osm = (float*)smr;                 // 64 x 33 floats = 8448 B
#pragma unroll
    for (int nt = 0; nt < 4; ++nt) {
        int d0 = nt * 8 + (lane & 3) * 2;
        Osm[r0 * 33 + d0]     = accO[nt][0];
        Osm[r0 * 33 + d0 + 1] = accO[nt][1];
        Osm[r1 * 33 + d0]     = accO[nt][2];
        Osm[r1 * 33 + d0 + 1] = accO[nt][3];
    }
    __syncthreads();

    size_t obase = ((size_t)b << 20) + ((size_t)head << 17);
#pragma unroll
    for (int it = 0; it < 16; ++it) {
        int idx = it * 128 + tid;
        int d = idx >> 6, t = idx & 63;
        int yi = t >> 3, xi = t & 7;
        int gh = (wy * 8 + yi + 4) & 63;
        int gw = (wx * 8 + xi + 4) & 63;
        out[obase + ((size_t)d << 12) + gh * 64 + gw] = Osm[t * 33 + d];
    }
}

// ---------------------------------------------------------------------------
extern "C" void kernel_launch(void* const* d_in, const int* in_sizes, int n_in,
                              void* d_out, int out_size)
{
    (void)in_sizes; (void)n_in; (void)out_size;
    const float* x    = (const float*)d_in[0];
    const float* qkvw = (const float*)d_in[1];
    const float* qkvb = (const float*)d_in[2];
    const float* tbl  = (const float*)d_in[3];
    float* out = (float*)d_out;

    cudaFuncSetAttribute(qkv_mma_kernel,
                         cudaFuncAttributeMaxDynamicSharedMemorySize, 2 * STG);

    gather_split_kernel<<<NWIN_TOT, 256>>>(x);
    transW_kernel<<<192, 256>>>(qkvw);
    qkv_mma_kernel<<<dim3(6, 1024), 256, 2 * STG>>>(qkvb);
    attn_kernel<<<dim3(NWIN_TOT, HEADS), 128>>>(tbl, out);
}

// round 6
// speedup vs baseline: 2.3756x; 1.0762x over previous
#include <cuda_runtime.h>
#include <cuda_bf16.h>
#include <cstdint>

// ---------------------------------------------------------------------------
// WindowAttention (Swin shifted-window attention).
//   B=32, DIM=256, H=W=64, WIN=8, SHIFT=4, HEADS=8, HEAD_DIM=32, N=64
// R6: GEMM K-chunk 32, 2 stages x 41KB smem -> 2 CTAs/SM for overlap.
//     (R5: HMMA attention w/ register softmax; split-bf16 3-term everywhere.)
// ---------------------------------------------------------------------------

#define NWIN_TOT   2048
#define M_TOT      131072
#define C_DIM      256
#define N3C        768
#define HEADS      8
#define HD         32
#define NTOK       64
#define SCALE      0.17677669529663687f

__device__ __nv_bfloat16 g_Ahi[(size_t)M_TOT * C_DIM];
__device__ __nv_bfloat16 g_Alo[(size_t)M_TOT * C_DIM];
__device__ __nv_bfloat16 g_Bhi[(size_t)N3C * C_DIM];
__device__ __nv_bfloat16 g_Blo[(size_t)N3C * C_DIM];
__device__ float g_qkv[(size_t)3 * NWIN_TOT * HEADS * NTOK * HD];

#define QKV_STRIDE ((size_t)NWIN_TOT * HEADS * NTOK * HD)

// ------------------------------ helpers -----------------------------------
__device__ __forceinline__ uint32_t smem_u32(const void* p) {
    uint32_t a;
    asm("{ .reg .u64 t; cvta.to.shared.u64 t, %1; cvt.u32.u64 %0, t; }"
        : "=r"(a) : "l"(p));
    return a;
}

__device__ __forceinline__ void cp16(uint32_t saddr, const void* g) {
    asm volatile("cp.async.cg.shared.global [%0], [%1], 16;" :: "r"(saddr), "l"(g));
}
#define CP_COMMIT()  asm volatile("cp.async.commit_group;" ::: "memory")
#define CP_WAIT(N)   asm volatile("cp.async.wait_group %0;" :: "n"(N) : "memory")

#define LDSM_X4(r, addr) \
    asm volatile("ldmatrix.sync.aligned.m8n8.x4.shared.b16 {%0,%1,%2,%3}, [%4];" \
        : "=r"((r)[0]), "=r"((r)[1]), "=r"((r)[2]), "=r"((r)[3]) : "r"(addr))
#define LDSM_X4T(r, addr) \
    asm volatile("ldmatrix.sync.aligned.m8n8.x4.trans.shared.b16 {%0,%1,%2,%3}, [%4];" \
        : "=r"((r)[0]), "=r"((r)[1]), "=r"((r)[2]), "=r"((r)[3]) : "r"(addr))

#define MMA_BF16(d, a, b) \
    asm volatile("mma.sync.aligned.m16n8k16.row.col.f32.bf16.bf16.f32 " \
        "{%0,%1,%2,%3}, {%4,%5,%6,%7}, {%8,%9}, {%0,%1,%2,%3};" \
        : "+f"((d)[0]), "+f"((d)[1]), "+f"((d)[2]), "+f"((d)[3]) \
        : "r"((a)[0]), "r"((a)[1]), "r"((a)[2]), "r"((a)[3]), \
          "r"((b)[0]), "r"((b)[1]))

__device__ __forceinline__ void split_pack(float v0, float v1, float v2, float v3,
                                           uint2& ph, uint2& pl)
{
    __nv_bfloat16 h0 = __float2bfloat16(v0);
    __nv_bfloat16 h1 = __float2bfloat16(v1);
    __nv_bfloat16 h2 = __float2bfloat16(v2);
    __nv_bfloat16 h3 = __float2bfloat16(v3);
    __nv_bfloat16 l0 = __float2bfloat16(v0 - __bfloat162float(h0));
    __nv_bfloat16 l1 = __float2bfloat16(v1 - __bfloat162float(h1));
    __nv_bfloat16 l2 = __float2bfloat16(v2 - __bfloat162float(h2));
    __nv_bfloat16 l3 = __float2bfloat16(v3 - __bfloat162float(h3));
    ph.x = ((uint32_t)__bfloat16_as_ushort(h1) << 16) | __bfloat16_as_ushort(h0);
    ph.y = ((uint32_t)__bfloat16_as_ushort(h3) << 16) | __bfloat16_as_ushort(h2);
    pl.x = ((uint32_t)__bfloat16_as_ushort(l1) << 16) | __bfloat16_as_ushort(l0);
    pl.y = ((uint32_t)__bfloat16_as_ushort(l3) << 16) | __bfloat16_as_ushort(l2);
}

__device__ __forceinline__ void split_pack2(float x, float y, uint32_t& h, uint32_t& l)
{
    __nv_bfloat16 hx = __float2bfloat16(x);
    __nv_bfloat16 hy = __float2bfloat16(y);
    __nv_bfloat16 lx = __float2bfloat16(x - __bfloat162float(hx));
    __nv_bfloat16 ly = __float2bfloat16(y - __bfloat162float(hy));
    h = ((uint32_t)__bfloat16_as_ushort(hy) << 16) | __bfloat16_as_ushort(hx);
    l = ((uint32_t)__bfloat16_as_ushort(ly) << 16) | __bfloat16_as_ushort(lx);
}

// ---------------------------------------------------------------------------
// K0: gather + roll + window partition + fp32->bf16 hi/lo split
// ---------------------------------------------------------------------------
__global__ void __launch_bounds__(256)
gather_split_kernel(const float* __restrict__ x)
{
    __shared__ float sm[64 * 65];
    const int blk = blockIdx.x;
    const int b  = blk >> 6;
    const int wy = (blk >> 3) & 7;
    const int wx = blk & 7;
    const int tid = threadIdx.x;

    uint2* dh = (uint2*)g_Ahi + (size_t)blk * 4096;
    uint2* dl = (uint2*)g_Alo + (size_t)blk * 4096;
    const float* xb = x + ((size_t)b << 20);

#pragma unroll 1
    for (int cc = 0; cc < 4; ++cc) {
#pragma unroll
        for (int it = 0; it < 16; ++it) {
            int idx = it * 256 + tid;
            int cl = idx >> 6;
            int t  = idx & 63;
            int i = t >> 3, j = t & 7;
            int gh = (wy * 8 + i + 4) & 63;
            int gw = (wx * 8 + j + 4) & 63;
            sm[t * 65 + cl] = xb[((size_t)(cc * 64 + cl) << 12) + gh * 64 + gw];
        }
        __syncthreads();
#pragma unroll
        for (int it = 0; it < 4; ++it) {
            int idx = it * 256 + tid;
            int t  = idx >> 4;
            int cq = idx & 15;
            const float* s = sm + t * 65 + cq * 4;
            uint2 ph, pl;
            split_pack(s[0], s[1], s[2], s[3], ph, pl);
            dh[t * 64 + cc * 16 + cq] = ph;
            dl[t * 64 + cc * 16 + cq] = pl;
        }
        __syncthreads();
    }
}

// ---------------------------------------------------------------------------
// K0b: transpose qkv_w [K=256][N=768] -> B [N][K] bf16 hi/lo
// ---------------------------------------------------------------------------
__global__ void __launch_bounds__(256)
transW_kernel(const float* __restrict__ W)
{
    int g = blockIdx.x * 256 + threadIdx.x;
    int n = g >> 6;
    int k4 = (g & 63) * 4;
    float v[4];
#pragma unroll
    for (int r = 0; r < 4; ++r) v[r] = W[(size_t)(k4 + r) * N3C + n];
    uint2 ph, pl;
    split_pack(v[0], v[1], v[2], v[3], ph, pl);
    ((uint2*)g_Bhi)[(size_t)n * 64 + (k4 >> 2)] = ph;
    ((uint2*)g_Blo)[(size_t)n * 64 + (k4 >> 2)] = pl;
}

// ---------------------------------------------------------------------------
// K1: HMMA split-bf16 QKV GEMM. grid = (6, 1024), 256 threads (8 warps 4x2).
// Tile 128x128, K=256 in 8 chunks of 32, double buffer, 2 CTAs/SM.
// Row: 32 bf16 = 64B data + 16B pad = 80B stride (ldsm conflict-free).
// Stage = 4 arrays * 128 * 80B = 40960B; 2 stages = 81920B.
// ---------------------------------------------------------------------------
#define ROWB2 80
#define ARR2  (128 * ROWB2)
#define STG2  (4 * ARR2)

__global__ void __launch_bounds__(256, 2)
qkv_mma_kernel(const float* __restrict__ bias)
{
    extern __shared__ __align__(128) char dsm[];
    const uint32_t su = smem_u32(dsm);

    const int tid  = threadIdx.x;
    const int lane = tid & 31;
    const int wid  = tid >> 5;
    const int wm   = wid >> 1;            // 0..3 (M)
    const int wn   = wid & 1;             // 0..1 (N)
    const int n0   = blockIdx.x * 128;
    const int m0   = blockIdx.y * 128;

    const __nv_bfloat16* pAh = g_Ahi + (size_t)m0 * C_DIM;
    const __nv_bfloat16* pAl = g_Alo + (size_t)m0 * C_DIM;
    const __nv_bfloat16* pBh = g_Bhi + (size_t)n0 * C_DIM;
    const __nv_bfloat16* pBl = g_Blo + (size_t)n0 * C_DIM;

    const int ldSeg = tid & 3;            // 16B segment within 64B row
    const int ldRow = tid >> 2;           // 0..63

    const uint32_t aRow = (uint32_t)(wm * 32 + (lane & 15)) * ROWB2
                        + (uint32_t)(lane >> 4) * 16;
    const uint32_t bRow = (uint32_t)(wn * 64 + ((lane >> 4) << 3) + (lane & 7)) * ROWB2
                        + (uint32_t)((lane >> 3) & 1) * 16;

    float acc[2][8][4];
#pragma unroll
    for (int i = 0; i < 2; ++i)
#pragma unroll
        for (int j = 0; j < 8; ++j)
#pragma unroll
            for (int q = 0; q < 4; ++q) acc[i][j][q] = 0.f;

    auto load_chunk = [&](int c, int st) {
        const uint32_t sb = su + st * STG2;
        const int kb = c * 32 + ldSeg * 8;      // bf16 col within K
#pragma unroll
        for (int p = 0; p < 2; ++p) {
            int row = p * 64 + ldRow;
            uint32_t so = (uint32_t)row * ROWB2 + (uint32_t)ldSeg * 16;
            size_t gi = (size_t)row * C_DIM + kb;
            cp16(sb + 0 * ARR2 + so, pAh + gi);
            cp16(sb + 1 * ARR2 + so, pAl + gi);
            cp16(sb + 2 * ARR2 + so, pBh + gi);
            cp16(sb + 3 * ARR2 + so, pBl + gi);
        }
        CP_COMMIT();
    };

    load_chunk(0, 0);

#pragma unroll 1
    for (int c = 0; c < 8; ++c) {
        if (c < 7) { load_chunk(c + 1, (c + 1) & 1); CP_WAIT(1); }
        else       { CP_WAIT(0); }
        __syncthreads();

        const uint32_t sb  = su + (c & 1) * STG2;
        const uint32_t sAh = sb;
        const uint32_t sAl = sb + ARR2;
        const uint32_t sBh = sb + 2 * ARR2;
        const uint32_t sBl = sb + 3 * ARR2;

#pragma unroll
        for (int ks = 0; ks < 2; ++ks) {
            uint32_t ah[2][4], al[2][4];
#pragma unroll
            for (int mt = 0; mt < 2; ++mt) {
                uint32_t ao = aRow + (uint32_t)mt * (16 * ROWB2) + (uint32_t)ks * 32;
                LDSM_X4(ah[mt], sAh + ao);
                LDSM_X4(al[mt], sAl + ao);
            }
#pragma unroll
            for (int np = 0; np < 4; ++np) {
                uint32_t bo = bRow + (uint32_t)np * (16 * ROWB2) + (uint32_t)ks * 32;
                uint32_t bh[4], bl[4];
                LDSM_X4(bh, sBh + bo);
                LDSM_X4(bl, sBl + bo);
#pragma unroll
                for (int half = 0; half < 2; ++half) {
                    int nt = np * 2 + half;
                    MMA_BF16(acc[0][nt], ah[0], bh + half * 2);
                    MMA_BF16(acc[1][nt], ah[1], bh + half * 2);
                    MMA_BF16(acc[0][nt], ah[0], bl + half * 2);
                    MMA_BF16(acc[1][nt], ah[1], bl + half * 2);
                    MMA_BF16(acc[0][nt], al[0], bh + half * 2);
                    MMA_BF16(acc[1][nt], al[1], bh + half * 2);
                }
            }
        }
        __syncthreads();
    }

    // ---- epilogue: bias add + scatter to g_qkv[which][win][head][t][d] ----
#pragma unroll
    for (int nt = 0; nt < 8; ++nt) {
        const int n = n0 + wn * 64 + nt * 8 + (lane & 3) * 2;
        const float2 bv = *(const float2*)(bias + n);
        const int which = n >> 8;
        const int head  = (n >> 5) & 7;
        const int d     = n & 31;
        const size_t nbase = (size_t)which * QKV_STRIDE + (size_t)head * (NTOK * HD) + d;
#pragma unroll
        for (int mt = 0; mt < 2; ++mt) {
            const int mb = m0 + wm * 32 + mt * 16 + (lane >> 2);
#pragma unroll
            for (int h = 0; h < 2; ++h) {
                const int m   = mb + h * 8;
                const int win = m >> 6;
                const int t   = m & 63;
                float2 v;
                v.x = acc[mt][nt][h * 2 + 0] + bv.x;
                v.y = acc[mt][nt][h * 2 + 1] + bv.y;
                *(float2*)(g_qkv + nbase + ((size_t)win * (HEADS * NTOK * HD) + (size_t)t * HD)) = v;
            }
        }
    }
}

// ---------------------------------------------------------------------------
// K2: HMMA attention. grid = (2048, 8), 128 threads (4 warps, 16 rows each).
// ---------------------------------------------------------------------------
#define ASTRIDE 80
#define AQH 0
#define AQL 5120
#define AKH 10240
#define AKL 15360
#define AVH 20480
#define AVL 25600

__global__ void __launch_bounds__(128)
attn_kernel(const float* __restrict__ table,
            float* __restrict__ out)
{
    __shared__ __align__(16) char smr[30720];
    __shared__ float biasS[225];
    __shared__ int   regS[64];

    const int win  = blockIdx.x;
    const int head = blockIdx.y;
    const int b  = win >> 6;
    const int wy = (win >> 3) & 7;
    const int wx = win & 7;

    const int tid  = threadIdx.x;
    const int lane = tid & 31;
    const int wid  = tid >> 5;
    const uint32_t sb = smem_u32(smr);

    const float* qb = g_qkv + (((size_t)win * HEADS + head) << 11);
    const float* kb = qb + QKV_STRIDE;
    const float* vb = qb + 2 * QKV_STRIDE;

    {
        auto load_split = [&](const float* src, int off, float scale) {
#pragma unroll
            for (int it = 0; it < 8; ++it) {
                int idx2 = it * 128 + tid;
                int t  = idx2 >> 4;
                int dp = idx2 & 15;
                float2 v = ((const float2*)src)[idx2];
                uint32_t h, l;
                split_pack2(v.x * scale, v.y * scale, h, l);
                *(uint32_t*)(smr + off + t * ASTRIDE + dp * 4) = h;
                *(uint32_t*)(smr + off + 5120 + t * ASTRIDE + dp * 4) = l;
            }
        };
        load_split(qb, AQH, SCALE);
        load_split(kb, AKH, 1.0f);
        load_split(vb, AVH, 1.0f);
    }
    for (int i = tid; i < 225; i += 128) biasS[i] = table[i * 8 + head];
    if (tid < 64) {
        int yi = tid >> 3, xi = tid & 7;
        int h = wy * 8 + yi, w = wx * 8 + xi;
        int rh = (h < 56) ? 0 : ((h < 60) ? 1 : 2);
        int rw = (w < 56) ? 0 : ((w < 60) ? 1 : 2);
        regS[tid] = rh * 3 + rw;
    }
    __syncthreads();

    const int m0 = wid * 16;

    float accS[8][4];
#pragma unroll
    for (int i = 0; i < 8; ++i)
#pragma unroll
        for (int q = 0; q < 4; ++q) accS[i][q] = 0.f;

    const uint32_t aoff = (uint32_t)(m0 + (lane & 15)) * ASTRIDE + (uint32_t)(lane >> 4) * 16;
    const uint32_t koff = (uint32_t)(((lane >> 4) << 3) + (lane & 7)) * ASTRIDE
                        + (uint32_t)((lane >> 3) & 1) * 16;

#pragma unroll
    for (int kt = 0; kt < 2; ++kt) {
        uint32_t qh[4], ql[4];
        LDSM_X4(qh, sb + AQH + aoff + kt * 32);
        LDSM_X4(ql, sb + AQL + aoff + kt * 32);
#pragma unroll
        for (int np = 0; np < 4; ++np) {
            uint32_t kh[4], kl[4];
            uint32_t bo = koff + (uint32_t)np * (16 * ASTRIDE) + kt * 32;
            LDSM_X4(kh, sb + AKH + bo);
            LDSM_X4(kl, sb + AKL + bo);
#pragma unroll
            for (int half = 0; half < 2; ++half) {
                int nt = np * 2 + half;
                MMA_BF16(accS[nt], qh, kh + half * 2);
                MMA_BF16(accS[nt], qh, kl + half * 2);
                MMA_BF16(accS[nt], ql, kh + half * 2);
            }
        }
    }

    const int r0 = m0 + (lane >> 2);
    const int r1 = r0 + 8;
    const int yi0 = r0 >> 3, xi0 = r0 & 7, rg0 = regS[r0];
    const int yi1 = r1 >> 3, xi1 = r1 & 7, rg1 = regS[r1];
#pragma unroll
    for (int nt = 0; nt < 8; ++nt) {
#pragma unroll
        for (int e = 0; e < 2; ++e) {
            int s  = nt * 8 + (lane & 3) * 2 + e;
            int ys = s >> 3, xs = s & 7;
            int rs = regS[s];
            accS[nt][e]     += biasS[(yi0 - ys + 7) * 15 + (xi0 - xs + 7)]
                             + (rs != rg0 ? -100.0f : 0.0f);
            accS[nt][2 + e] += biasS[(yi1 - ys + 7) * 15 + (xi1 - xs + 7)]
                             + (rs != rg1 ? -100.0f : 0.0f);
        }
    }

    {
        float mx0 = -1e30f, mx1 = -1e30f;
#pragma unroll
        for (int nt = 0; nt < 8; ++nt) {
            mx0 = fmaxf(mx0, fmaxf(accS[nt][0], accS[nt][1]));
            mx1 = fmaxf(mx1, fmaxf(accS[nt][2], accS[nt][3]));
        }
#pragma unroll
        for (int o = 1; o < 4; o <<= 1) {
            mx0 = fmaxf(mx0, __shfl_xor_sync(0xFFFFFFFF, mx0, o));
            mx1 = fmaxf(mx1, __shfl_xor_sync(0xFFFFFFFF, mx1, o));
        }
        float sum0 = 0.f, sum1 = 0.f;
#pragma unroll
        for (int nt = 0; nt < 8; ++nt) {
            accS[nt][0] = __expf(accS[nt][0] - mx0);
            accS[nt][1] = __expf(accS[nt][1] - mx0);
            accS[nt][2] = __expf(accS[nt][2] - mx1);
            accS[nt][3] = __expf(accS[nt][3] - mx1);
            sum0 += accS[nt][0] + accS[nt][1];
            sum1 += accS[nt][2] + accS[nt][3];
        }
#pragma unroll
        for (int o = 1; o < 4; o <<= 1) {
            sum0 += __shfl_xor_sync(0xFFFFFFFF, sum0, o);
            sum1 += __shfl_xor_sync(0xFFFFFFFF, sum1, o);
        }
        float inv0 = 1.0f / sum0, inv1 = 1.0f / sum1;
#pragma unroll
        for (int nt = 0; nt < 8; ++nt) {
            accS[nt][0] *= inv0; accS[nt][1] *= inv0;
            accS[nt][2] *= inv1; accS[nt][3] *= inv1;
        }
    }

    uint32_t ph[4][4], pl[4][4];
#pragma unroll
    for (int kt = 0; kt < 4; ++kt) {
        split_pack2(accS[2 * kt][0],     accS[2 * kt][1],     ph[kt][0], pl[kt][0]);
        split_pack2(accS[2 * kt][2],     accS[2 * kt][3],     ph[kt][1], pl[kt][1]);
        split_pack2(accS[2 * kt + 1][0], accS[2 * kt + 1][1], ph[kt][2], pl[kt][2]);
        split_pack2(accS[2 * kt + 1][2], accS[2 * kt + 1][3], ph[kt][3], pl[kt][3]);
    }

    float accO[4][4];
#pragma unroll
    for (int i = 0; i < 4; ++i)
#pragma unroll
        for (int q = 0; q < 4; ++q) accO[i][q] = 0.f;

    const uint32_t vrow = (uint32_t)((lane & 7) + ((lane >> 3) & 1) * 8) * ASTRIDE
                        + (uint32_t)((lane >> 4) << 3) * 2;
#pragma unroll
    for (int kt = 0; kt < 4; ++kt) {
#pragma unroll
        for (int np = 0; np < 2; ++np) {
            uint32_t vh[4], vl[4];
            uint32_t vo = vrow + (uint32_t)kt * (16 * ASTRIDE) + (uint32_t)np * 32;
            LDSM_X4T(vh, sb + AVH + vo);
            LDSM_X4T(vl, sb + AVL + vo);
#pragma unroll
            for (int half = 0; half < 2; ++half) {
                int nt = np * 2 + half;
                MMA_BF16(accO[nt], ph[kt], vh + half * 2);
                MMA_BF16(accO[nt], ph[kt], vl + half * 2);
                MMA_BF16(accO[nt], pl[kt], vh + half * 2);
            }
        }
    }

    __syncthreads();
    float* Osm = (float*)smr;
#pragma unroll
    for (int nt = 0; nt < 4; ++nt) {
        int d0 = nt * 8 + (lane & 3) * 2;
        Osm[r0 * 33 + d0]     = accO[nt][0];
        Osm[r0 * 33 + d0 + 1] = accO[nt][1];
        Osm[r1 * 33 + d0]     = accO[nt][2];
        Osm[r1 * 33 + d0 + 1] = accO[nt][3];
    }
    __syncthreads();

    size_t obase = ((size_t)b << 20) + ((size_t)head << 17);
#pragma unroll
    for (int it = 0; it < 16; ++it) {
        int idx = it * 128 + tid;
        int d = idx >> 6, t = idx & 63;
        int yi = t >> 3, xi = t & 7;
        int gh = (wy * 8 + yi + 4) & 63;
        int gw = (wx * 8 + xi + 4) & 63;
        out[obase + ((size_t)d << 12) + gh * 64 + gw] = Osm[t * 33 + d];
    }
}

// ---------------------------------------------------------------------------
extern "C" void kernel_launch(void* const* d_in, const int* in_sizes, int n_in,
                              void* d_out, int out_size)
{
    (void)in_sizes; (void)n_in; (void)out_size;
    const float* x    = (const float*)d_in[0];
    const float* qkvw = (const float*)d_in[1];
    const float* qkvb = (const float*)d_in[2];
    const float* tbl  = (const float*)d_in[3];
    float* out = (float*)d_out;

    cudaFuncSetAttribute(qkv_mma_kernel,
                         cudaFuncAttributeMaxDynamicSharedMemorySize, 2 * STG2);

    gather_split_kernel<<<NWIN_TOT, 256>>>(x);
    transW_kernel<<<192, 256>>>(qkvw);
    qkv_mma_kernel<<<dim3(6, 1024), 256, 2 * STG2>>>(qkvb);
    attn_kernel<<<dim3(NWIN_TOT, HEADS), 128>>>(tbl, out);
}

// round 7
// speedup vs baseline: 3.4015x; 1.4318x over previous
#include <cuda_runtime.h>
#include <cuda_bf16.h>
#include <cuda_fp16.h>
#include <cstdint>

// ---------------------------------------------------------------------------
// WindowAttention (Swin shifted-window attention).
//   B=32, DIM=256, H=W=64, WIN=8, SHIFT=4, HEADS=8, HEAD_DIM=32, N=64
// R7: QKV GEMM single-pass fp16 HMMA (fp32 accumulate) — 3x less tensor work
//     than R6's split-bf16. Attention stays split-bf16 (R5).
// ---------------------------------------------------------------------------

#define NWIN_TOT   2048
#define M_TOT      131072
#define C_DIM      256
#define N3C        768
#define HEADS      8
#define HD         32
#define NTOK       64
#define SCALE      0.17677669529663687f

__device__ __half g_Ah[(size_t)M_TOT * C_DIM];
__device__ __half g_Bh[(size_t)N3C * C_DIM];
__device__ float g_qkv[(size_t)3 * NWIN_TOT * HEADS * NTOK * HD];

#define QKV_STRIDE ((size_t)NWIN_TOT * HEADS * NTOK * HD)

// ------------------------------ helpers -----------------------------------
__device__ __forceinline__ uint32_t smem_u32(const void* p) {
    uint32_t a;
    asm("{ .reg .u64 t; cvta.to.shared.u64 t, %1; cvt.u32.u64 %0, t; }"
        : "=r"(a) : "l"(p));
    return a;
}

__device__ __forceinline__ void cp16(uint32_t saddr, const void* g) {
    asm volatile("cp.async.cg.shared.global [%0], [%1], 16;" :: "r"(saddr), "l"(g));
}
#define CP_COMMIT()  asm volatile("cp.async.commit_group;" ::: "memory")
#define CP_WAIT(N)   asm volatile("cp.async.wait_group %0;" :: "n"(N) : "memory")

#define LDSM_X4(r, addr) \
    asm volatile("ldmatrix.sync.aligned.m8n8.x4.shared.b16 {%0,%1,%2,%3}, [%4];" \
        : "=r"((r)[0]), "=r"((r)[1]), "=r"((r)[2]), "=r"((r)[3]) : "r"(addr))
#define LDSM_X4T(r, addr) \
    asm volatile("ldmatrix.sync.aligned.m8n8.x4.trans.shared.b16 {%0,%1,%2,%3}, [%4];" \
        : "=r"((r)[0]), "=r"((r)[1]), "=r"((r)[2]), "=r"((r)[3]) : "r"(addr))

#define MMA_BF16(d, a, b) \
    asm volatile("mma.sync.aligned.m16n8k16.row.col.f32.bf16.bf16.f32 " \
        "{%0,%1,%2,%3}, {%4,%5,%6,%7}, {%8,%9}, {%0,%1,%2,%3};" \
        : "+f"((d)[0]), "+f"((d)[1]), "+f"((d)[2]), "+f"((d)[3]) \
        : "r"((a)[0]), "r"((a)[1]), "r"((a)[2]), "r"((a)[3]), \
          "r"((b)[0]), "r"((b)[1]))

#define MMA_F16(d, a, b) \
    asm volatile("mma.sync.aligned.m16n8k16.row.col.f32.f16.f16.f32 " \
        "{%0,%1,%2,%3}, {%4,%5,%6,%7}, {%8,%9}, {%0,%1,%2,%3};" \
        : "+f"((d)[0]), "+f"((d)[1]), "+f"((d)[2]), "+f"((d)[3]) \
        : "r"((a)[0]), "r"((a)[1]), "r"((a)[2]), "r"((a)[3]), \
          "r"((b)[0]), "r"((b)[1]))

// pack 4 floats -> 4 fp16 in uint2
__device__ __forceinline__ uint2 pack4h(float v0, float v1, float v2, float v3)
{
    uint2 r;
    __half2 a = __floats2half2_rn(v0, v1);
    __half2 b = __floats2half2_rn(v2, v3);
    r.x = *(uint32_t*)&a;
    r.y = *(uint32_t*)&b;
    return r;
}

__device__ __forceinline__ void split_pack2(float x, float y, uint32_t& h, uint32_t& l)
{
    __nv_bfloat16 hx = __float2bfloat16(x);
    __nv_bfloat16 hy = __float2bfloat16(y);
    __nv_bfloat16 lx = __float2bfloat16(x - __bfloat162float(hx));
    __nv_bfloat16 ly = __float2bfloat16(y - __bfloat162float(hy));
    h = ((uint32_t)__bfloat16_as_ushort(hy) << 16) | __bfloat16_as_ushort(hx);
    l = ((uint32_t)__bfloat16_as_ushort(ly) << 16) | __bfloat16_as_ushort(lx);
}

// ---------------------------------------------------------------------------
// K0: gather + roll + window partition + fp32->fp16
// grid = 2048 (b,win), 256 threads; 4 chunks of 64 channels via smem transpose
// ---------------------------------------------------------------------------
__global__ void __launch_bounds__(256)
gather_split_kernel(const float* __restrict__ x)
{
    __shared__ float sm[64 * 65];
    const int blk = blockIdx.x;
    const int b  = blk >> 6;
    const int wy = (blk >> 3) & 7;
    const int wx = blk & 7;
    const int tid = threadIdx.x;

    uint2* dh = (uint2*)g_Ah + (size_t)blk * 4096;
    const float* xb = x + ((size_t)b << 20);

#pragma unroll 1
    for (int cc = 0; cc < 4; ++cc) {
#pragma unroll
        for (int it = 0; it < 16; ++it) {
            int idx = it * 256 + tid;
            int cl = idx >> 6;
            int t  = idx & 63;
            int i = t >> 3, j = t & 7;
            int gh = (wy * 8 + i + 4) & 63;
            int gw = (wx * 8 + j + 4) & 63;
            sm[t * 65 + cl] = xb[((size_t)(cc * 64 + cl) << 12) + gh * 64 + gw];
        }
        __syncthreads();
#pragma unroll
        for (int it = 0; it < 4; ++it) {
            int idx = it * 256 + tid;
            int t  = idx >> 4;
            int cq = idx & 15;
            const float* s = sm + t * 65 + cq * 4;
            dh[t * 64 + cc * 16 + cq] = pack4h(s[0], s[1], s[2], s[3]);
        }
        __syncthreads();
    }
}

// ---------------------------------------------------------------------------
// K0b: transpose qkv_w [K=256][N=768] -> B [N][K] fp16
// ---------------------------------------------------------------------------
__global__ void __launch_bounds__(256)
transW_kernel(const float* __restrict__ W)
{
    int g = blockIdx.x * 256 + threadIdx.x;
    int n = g >> 6;
    int k4 = (g & 63) * 4;
    float v[4];
#pragma unroll
    for (int r = 0; r < 4; ++r) v[r] = W[(size_t)(k4 + r) * N3C + n];
    ((uint2*)g_Bh)[(size_t)n * 64 + (k4 >> 2)] = pack4h(v[0], v[1], v[2], v[3]);
}

// ---------------------------------------------------------------------------
// K1: fp16 HMMA QKV GEMM. grid = (6, 1024), 256 threads (8 warps 4x2).
// Tile 128x128, K=256 in 8 chunks of 32, double buffer, 2 CTAs/SM.
// Row: 32 fp16 = 64B data + 16B pad = 80B stride.
// Stage = 2 arrays * 128 * 80B = 20480B; 2 stages = 40960B.
// ---------------------------------------------------------------------------
#define ROWB2 80
#define ARR2  (128 * ROWB2)
#define STG2  (2 * ARR2)

__global__ void __launch_bounds__(256, 2)
qkv_mma_kernel(const float* __restrict__ bias)
{
    extern __shared__ __align__(128) char dsm[];
    const uint32_t su = smem_u32(dsm);

    const int tid  = threadIdx.x;
    const int lane = tid & 31;
    const int wid  = tid >> 5;
    const int wm   = wid >> 1;            // 0..3 (M)
    const int wn   = wid & 1;             // 0..1 (N)
    const int n0   = blockIdx.x * 128;
    const int m0   = blockIdx.y * 128;

    const __half* pA = g_Ah + (size_t)m0 * C_DIM;
    const __half* pB = g_Bh + (size_t)n0 * C_DIM;

    const int ldSeg = tid & 3;            // 16B segment within 64B row
    const int ldRow = tid >> 2;           // 0..63

    const uint32_t aRow = (uint32_t)(wm * 32 + (lane & 15)) * ROWB2
                        + (uint32_t)(lane >> 4) * 16;
    const uint32_t bRow = (uint32_t)(wn * 64 + ((lane >> 4) << 3) + (lane & 7)) * ROWB2
                        + (uint32_t)((lane >> 3) & 1) * 16;

    float acc[2][8][4];
#pragma unroll
    for (int i = 0; i < 2; ++i)
#pragma unroll
        for (int j = 0; j < 8; ++j)
#pragma unroll
            for (int q = 0; q < 4; ++q) acc[i][j][q] = 0.f;

    auto load_chunk = [&](int c, int st) {
        const uint32_t sb = su + st * STG2;
        const int kb = c * 32 + ldSeg * 8;      // fp16 col within K
#pragma unroll
        for (int p = 0; p < 2; ++p) {
            int row = p * 64 + ldRow;
            uint32_t so = (uint32_t)row * ROWB2 + (uint32_t)ldSeg * 16;
            size_t gi = (size_t)row * C_DIM + kb;
            cp16(sb + so,        pA + gi);
            cp16(sb + ARR2 + so, pB + gi);
        }
        CP_COMMIT();
    };

    load_chunk(0, 0);

#pragma unroll 1
    for (int c = 0; c < 8; ++c) {
        if (c < 7) { load_chunk(c + 1, (c + 1) & 1); CP_WAIT(1); }
        else       { CP_WAIT(0); }
        __syncthreads();

        const uint32_t sb = su + (c & 1) * STG2;
        const uint32_t sA = sb;
        const uint32_t sB = sb + ARR2;

#pragma unroll
        for (int ks = 0; ks < 2; ++ks) {
            uint32_t ah[2][4];
#pragma unroll
            for (int mt = 0; mt < 2; ++mt) {
                uint32_t ao = aRow + (uint32_t)mt * (16 * ROWB2) + (uint32_t)ks * 32;
                LDSM_X4(ah[mt], sA + ao);
            }
#pragma unroll
            for (int np = 0; np < 4; ++np) {
                uint32_t bo = bRow + (uint32_t)np * (16 * ROWB2) + (uint32_t)ks * 32;
                uint32_t bh[4];
                LDSM_X4(bh, sB + bo);
#pragma unroll
                for (int half = 0; half < 2; ++half) {
                    int nt = np * 2 + half;
                    MMA_F16(acc[0][nt], ah[0], bh + half * 2);
                    MMA_F16(acc[1][nt], ah[1], bh + half * 2);
                }
            }
        }
        __syncthreads();
    }

    // ---- epilogue: bias add + scatter to g_qkv[which][win][head][t][d] ----
#pragma unroll
    for (int nt = 0; nt < 8; ++nt) {
        const int n = n0 + wn * 64 + nt * 8 + (lane & 3) * 2;
        const float2 bv = *(const float2*)(bias + n);
        const int which = n >> 8;
        const int head  = (n >> 5) & 7;
        const int d     = n & 31;
        const size_t nbase = (size_t)which * QKV_STRIDE + (size_t)head * (NTOK * HD) + d;
#pragma unroll
        for (int mt = 0; mt < 2; ++mt) {
            const int mb = m0 + wm * 32 + mt * 16 + (lane >> 2);
#pragma unroll
            for (int h = 0; h < 2; ++h) {
                const int m   = mb + h * 8;
                const int win = m >> 6;
                const int t   = m & 63;
                float2 v;
                v.x = acc[mt][nt][h * 2 + 0] + bv.x;
                v.y = acc[mt][nt][h * 2 + 1] + bv.y;
                *(float2*)(g_qkv + nbase + ((size_t)win * (HEADS * NTOK * HD) + (size_t)t * HD)) = v;
            }
        }
    }
}

// ---------------------------------------------------------------------------
// K2: HMMA attention. grid = (2048, 8), 128 threads (4 warps, 16 rows each).
// Q/K/V split hi/lo bf16 in smem; register softmax; 3-term split MMA.
// ---------------------------------------------------------------------------
#define ASTRIDE 80
#define AQH 0
#define AQL 5120
#define AKH 10240
#define AKL 15360
#define AVH 20480
#define AVL 25600

__global__ void __launch_bounds__(128)
attn_kernel(const float* __restrict__ table,
            float* __restrict__ out)
{
    __shared__ __align__(16) char smr[30720];
    __shared__ float biasS[225];
    __shared__ int   regS[64];

    const int win  = blockIdx.x;
    const int head = blockIdx.y;
    const int b  = win >> 6;
    const int wy = (win >> 3) & 7;
    const int wx = win & 7;

    const int tid  = threadIdx.x;
    const int lane = tid & 31;
    const int wid  = tid >> 5;
    const uint32_t sb = smem_u32(smr);

    const float* qb = g_qkv + (((size_t)win * HEADS + head) << 11);
    const float* kb = qb + QKV_STRIDE;
    const float* vb = qb + 2 * QKV_STRIDE;

    {
        auto load_split = [&](const float* src, int off, float scale) {
#pragma unroll
            for (int it = 0; it < 8; ++it) {
                int idx2 = it * 128 + tid;
                int t  = idx2 >> 4;
                int dp = idx2 & 15;
                float2 v = ((const float2*)src)[idx2];
                uint32_t h, l;
                split_pack2(v.x * scale, v.y * scale, h, l);
                *(uint32_t*)(smr + off + t * ASTRIDE + dp * 4) = h;
                *(uint32_t*)(smr + off + 5120 + t * ASTRIDE + dp * 4) = l;
            }
        };
        load_split(qb, AQH, SCALE);
        load_split(kb, AKH, 1.0f);
        load_split(vb, AVH, 1.0f);
    }
    for (int i = tid; i < 225; i += 128) biasS[i] = table[i * 8 + head];
    if (tid < 64) {
        int yi = tid >> 3, xi = tid & 7;
        int h = wy * 8 + yi, w = wx * 8 + xi;
        int rh = (h < 56) ? 0 : ((h < 60) ? 1 : 2);
        int rw = (w < 56) ? 0 : ((w < 60) ? 1 : 2);
        regS[tid] = rh * 3 + rw;
    }
    __syncthreads();

    const int m0 = wid * 16;

    float accS[8][4];
#pragma unroll
    for (int i = 0; i < 8; ++i)
#pragma unroll
        for (int q = 0; q < 4; ++q) accS[i][q] = 0.f;

    const uint32_t aoff = (uint32_t)(m0 + (lane & 15)) * ASTRIDE + (uint32_t)(lane >> 4) * 16;
    const uint32_t koff = (uint32_t)(((lane >> 4) << 3) + (lane & 7)) * ASTRIDE
                        + (uint32_t)((lane >> 3) & 1) * 16;

#pragma unroll
    for (int kt = 0; kt < 2; ++kt) {
        uint32_t qh[4], ql[4];
        LDSM_X4(qh, sb + AQH + aoff + kt * 32);
        LDSM_X4(ql, sb + AQL + aoff + kt * 32);
#pragma unroll
        for (int np = 0; np < 4; ++np) {
            uint32_t kh[4], kl[4];
            uint32_t bo = koff + (uint32_t)np * (16 * ASTRIDE) + kt * 32;
            LDSM_X4(kh, sb + AKH + bo);
            LDSM_X4(kl, sb + AKL + bo);
#pragma unroll
            for (int half = 0; half < 2; ++half) {
                int nt = np * 2 + half;
                MMA_BF16(accS[nt], qh, kh + half * 2);
                MMA_BF16(accS[nt], qh, kl + half * 2);
                MMA_BF16(accS[nt], ql, kh + half * 2);
            }
        }
    }

    const int r0 = m0 + (lane >> 2);
    const int r1 = r0 + 8;
    const int yi0 = r0 >> 3, xi0 = r0 & 7, rg0 = regS[r0];
    const int yi1 = r1 >> 3, xi1 = r1 & 7, rg1 = regS[r1];
#pragma unroll
    for (int nt = 0; nt < 8; ++nt) {
#pragma unroll
        for (int e = 0; e < 2; ++e) {
            int s  = nt * 8 + (lane & 3) * 2 + e;
            int ys = s >> 3, xs = s & 7;
            int rs = regS[s];
            accS[nt][e]     += biasS[(yi0 - ys + 7) * 15 + (xi0 - xs + 7)]
                             + (rs != rg0 ? -100.0f : 0.0f);
            accS[nt][2 + e] += biasS[(yi1 - ys + 7) * 15 + (xi1 - xs + 7)]
                             + (rs != rg1 ? -100.0f : 0.0f);
        }
    }

    {
        float mx0 = -1e30f, mx1 = -1e30f;
#pragma unroll
        for (int nt = 0; nt < 8; ++nt) {
            mx0 = fmaxf(mx0, fmaxf(accS[nt][0], accS[nt][1]));
            mx1 = fmaxf(mx1, fmaxf(accS[nt][2], accS[nt][3]));
        }
#pragma unroll
        for (int o = 1; o < 4; o <<= 1) {
            mx0 = fmaxf(mx0, __shfl_xor_sync(0xFFFFFFFF, mx0, o));
            mx1 = fmaxf(mx1, __shfl_xor_sync(0xFFFFFFFF, mx1, o));
        }
        float sum0 = 0.f, sum1 = 0.f;
#pragma unroll
        for (int nt = 0; nt < 8; ++nt) {
            accS[nt][0] = __expf(accS[nt][0] - mx0);
            accS[nt][1] = __expf(accS[nt][1] - mx0);
            accS[nt][2] = __expf(accS[nt][2] - mx1);
            accS[nt][3] = __expf(accS[nt][3] - mx1);
            sum0 += accS[nt][0] + accS[nt][1];
            sum1 += accS[nt][2] + accS[nt][3];
        }
#pragma unroll
        for (int o = 1; o < 4; o <<= 1) {
            sum0 += __shfl_xor_sync(0xFFFFFFFF, sum0, o);
            sum1 += __shfl_xor_sync(0xFFFFFFFF, sum1, o);
        }
        float inv0 = 1.0f / sum0, inv1 = 1.0f / sum1;
#pragma unroll
        for (int nt = 0; nt < 8; ++nt) {
            accS[nt][0] *= inv0; accS[nt][1] *= inv0;
            accS[nt][2] *= inv1; accS[nt][3] *= inv1;
        }
    }

    uint32_t ph[4][4], pl[4][4];
#pragma unroll
    for (int kt = 0; kt < 4; ++kt) {
        split_pack2(accS[2 * kt][0],     accS[2 * kt][1],     ph[kt][0], pl[kt][0]);
        split_pack2(accS[2 * kt][2],     accS[2 * kt][3],     ph[kt][1], pl[kt][1]);
        split_pack2(accS[2 * kt + 1][0], accS[2 * kt + 1][1], ph[kt][2], pl[kt][2]);
        split_pack2(accS[2 * kt + 1][2], accS[2 * kt + 1][3], ph[kt][3], pl[kt][3]);
    }

    float accO[4][4];
#pragma unroll
    for (int i = 0; i < 4; ++i)
#pragma unroll
        for (int q = 0; q < 4; ++q) accO[i][q] = 0.f;

    const uint32_t vrow = (uint32_t)((lane & 7) + ((lane >> 3) & 1) * 8) * ASTRIDE
                        + (uint32_t)((lane >> 4) << 3) * 2;
#pragma unroll
    for (int kt = 0; kt < 4; ++kt) {
#pragma unroll
        for (int np = 0; np < 2; ++np) {
            uint32_t vh[4], vl[4];
            uint32_t vo = vrow + (uint32_t)kt * (16 * ASTRIDE) + (uint32_t)np * 32;
            LDSM_X4T(vh, sb + AVH + vo);
            LDSM_X4T(vl, sb + AVL + vo);
#pragma unroll
            for (int half = 0; half < 2; ++half) {
                int nt = np * 2 + half;
                MMA_BF16(accO[nt], ph[kt], vh + half * 2);
                MMA_BF16(accO[nt], ph[kt], vl + half * 2);
                MMA_BF16(accO[nt], pl[kt], vh + half * 2);
            }
        }
    }

    __syncthreads();
    float* Osm = (float*)smr;
#pragma unroll
    for (int nt = 0; nt < 4; ++nt) {
        int d0 = nt * 8 + (lane & 3) * 2;
        Osm[r0 * 33 + d0]     = accO[nt][0];
        Osm[r0 * 33 + d0 + 1] = accO[nt][1];
        Osm[r1 * 33 + d0]     = accO[nt][2];
        Osm[r1 * 33 + d0 + 1] = accO[nt][3];
    }
    __syncthreads();

    size_t obase = ((size_t)b << 20) + ((size_t)head << 17);
#pragma unroll
    for (int it = 0; it < 16; ++it) {
        int idx = it * 128 + tid;
        int d = idx >> 6, t = idx & 63;
        int yi = t >> 3, xi = t & 7;
        int gh = (wy * 8 + yi + 4) & 63;
        int gw = (wx * 8 + xi + 4) & 63;
        out[obase + ((size_t)d << 12) + gh * 64 + gw] = Osm[t * 33 + d];
    }
}

// ---------------------------------------------------------------------------
extern "C" void kernel_launch(void* const* d_in, const int* in_sizes, int n_in,
                              void* d_out, int out_size)
{
    (void)in_sizes; (void)n_in; (void)out_size;
    const float* x    = (const float*)d_in[0];
    const float* qkvw = (const float*)d_in[1];
    const float* qkvb = (const float*)d_in[2];
    const float* tbl  = (const float*)d_in[3];
    float* out = (float*)d_out;

    cudaFuncSetAttribute(qkv_mma_kernel,
                         cudaFuncAttributeMaxDynamicSharedMemorySize, 2 * STG2);

    gather_split_kernel<<<NWIN_TOT, 256>>>(x);
    transW_kernel<<<192, 256>>>(qkvw);
    qkv_mma_kernel<<<dim3(6, 1024), 256, 2 * STG2>>>(qkvb);
    attn_kernel<<<dim3(NWIN_TOT, HEADS), 128>>>(tbl, out);
}

// round 8
// speedup vs baseline: 3.8818x; 1.1412x over previous
#include <cuda_runtime.h>
#include <cuda_bf16.h>
#include <cuda_fp16.h>
#include <cstdint>

// ---------------------------------------------------------------------------
// WindowAttention (Swin shifted-window attention).
//   B=32, DIM=256, H=W=64, WIN=8, SHIFT=4, HEADS=8, HEAD_DIM=32, N=64
// R8: fp16 single-pass everywhere (GEMM + attention), fp32 accumulate.
//     GEMM: 4-stage cp.async pipeline, 1 sync per chunk, 2 CTAs/SM.
//     Attention: register softmax (fp32), fp16 HMMA for S and PV.
// ---------------------------------------------------------------------------

#define NWIN_TOT   2048
#define M_TOT      131072
#define C_DIM      256
#define N3C        768
#define HEADS      8
#define HD         32
#define NTOK       64
#define SCALE      0.17677669529663687f

__device__ __half g_Ah[(size_t)M_TOT * C_DIM];
__device__ __half g_Bh[(size_t)N3C * C_DIM];
__device__ float g_qkv[(size_t)3 * NWIN_TOT * HEADS * NTOK * HD];

#define QKV_STRIDE ((size_t)NWIN_TOT * HEADS * NTOK * HD)

// ------------------------------ helpers -----------------------------------
__device__ __forceinline__ uint32_t smem_u32(const void* p) {
    uint32_t a;
    asm("{ .reg .u64 t; cvta.to.shared.u64 t, %1; cvt.u32.u64 %0, t; }"
        : "=r"(a) : "l"(p));
    return a;
}

__device__ __forceinline__ void cp16(uint32_t saddr, const void* g) {
    asm volatile("cp.async.cg.shared.global [%0], [%1], 16;" :: "r"(saddr), "l"(g));
}
#define CP_COMMIT()  asm volatile("cp.async.commit_group;" ::: "memory")
#define CP_WAIT(N)   asm volatile("cp.async.wait_group %0;" :: "n"(N) : "memory")

#define LDSM_X4(r, addr) \
    asm volatile("ldmatrix.sync.aligned.m8n8.x4.shared.b16 {%0,%1,%2,%3}, [%4];" \
        : "=r"((r)[0]), "=r"((r)[1]), "=r"((r)[2]), "=r"((r)[3]) : "r"(addr))
#define LDSM_X4T(r, addr) \
    asm volatile("ldmatrix.sync.aligned.m8n8.x4.trans.shared.b16 {%0,%1,%2,%3}, [%4];" \
        : "=r"((r)[0]), "=r"((r)[1]), "=r"((r)[2]), "=r"((r)[3]) : "r"(addr))

#define MMA_F16(d, a, b) \
    asm volatile("mma.sync.aligned.m16n8k16.row.col.f32.f16.f16.f32 " \
        "{%0,%1,%2,%3}, {%4,%5,%6,%7}, {%8,%9}, {%0,%1,%2,%3};" \
        : "+f"((d)[0]), "+f"((d)[1]), "+f"((d)[2]), "+f"((d)[3]) \
        : "r"((a)[0]), "r"((a)[1]), "r"((a)[2]), "r"((a)[3]), \
          "r"((b)[0]), "r"((b)[1]))

__device__ __forceinline__ uint32_t pack2h(float x, float y)
{
    __half2 a = __floats2half2_rn(x, y);
    return *(uint32_t*)&a;
}
__device__ __forceinline__ uint2 pack4h(float v0, float v1, float v2, float v3)
{
    uint2 r;
    r.x = pack2h(v0, v1);
    r.y = pack2h(v2, v3);
    return r;
}

// ---------------------------------------------------------------------------
// K0: gather + roll + window partition + fp32->fp16
// ---------------------------------------------------------------------------
__global__ void __launch_bounds__(256)
gather_split_kernel(const float* __restrict__ x)
{
    __shared__ float sm[64 * 65];
    const int blk = blockIdx.x;
    const int b  = blk >> 6;
    const int wy = (blk >> 3) & 7;
    const int wx = blk & 7;
    const int tid = threadIdx.x;

    uint2* dh = (uint2*)g_Ah + (size_t)blk * 4096;
    const float* xb = x + ((size_t)b << 20);

#pragma unroll 1
    for (int cc = 0; cc < 4; ++cc) {
#pragma unroll
        for (int it = 0; it < 16; ++it) {
            int idx = it * 256 + tid;
            int cl = idx >> 6;
            int t  = idx & 63;
            int i = t >> 3, j = t & 7;
            int gh = (wy * 8 + i + 4) & 63;
            int gw = (wx * 8 + j + 4) & 63;
            sm[t * 65 + cl] = xb[((size_t)(cc * 64 + cl) << 12) + gh * 64 + gw];
        }
        __syncthreads();
#pragma unroll
        for (int it = 0; it < 4; ++it) {
            int idx = it * 256 + tid;
            int t  = idx >> 4;
            int cq = idx & 15;
            const float* s = sm + t * 65 + cq * 4;
            dh[t * 64 + cc * 16 + cq] = pack4h(s[0], s[1], s[2], s[3]);
        }
        __syncthreads();
    }
}

// ---------------------------------------------------------------------------
// K0b: transpose qkv_w [K=256][N=768] -> B [N][K] fp16
// ---------------------------------------------------------------------------
__global__ void __launch_bounds__(256)
transW_kernel(const float* __restrict__ W)
{
    int g = blockIdx.x * 256 + threadIdx.x;
    int n = g >> 6;
    int k4 = (g & 63) * 4;
    float v[4];
#pragma unroll
    for (int r = 0; r < 4; ++r) v[r] = W[(size_t)(k4 + r) * N3C + n];
    ((uint2*)g_Bh)[(size_t)n * 64 + (k4 >> 2)] = pack4h(v[0], v[1], v[2], v[3]);
}

// ---------------------------------------------------------------------------
// K1: fp16 HMMA QKV GEMM. grid = (6, 1024), 256 threads (8 warps 4x2).
// Tile 128x128, K=256 in 8 chunks of 32, 4-stage pipeline, 2 CTAs/SM.
// Stage = 2 arrays * 128 rows * 80B = 20480B; 4 stages = 81920B.
// ---------------------------------------------------------------------------
#define ROWB2 80
#define ARR2  (128 * ROWB2)
#define STG2  (2 * ARR2)
#define NSTG  4

__global__ void __launch_bounds__(256, 2)
qkv_mma_kernel(const float* __restrict__ bias)
{
    extern __shared__ __align__(128) char dsm[];
    const uint32_t su = smem_u32(dsm);

    const int tid  = threadIdx.x;
    const int lane = tid & 31;
    const int wid  = tid >> 5;
    const int wm   = wid >> 1;
    const int wn   = wid & 1;
    const int n0   = blockIdx.x * 128;
    const int m0   = blockIdx.y * 128;

    const __half* pA = g_Ah + (size_t)m0 * C_DIM;
    const __half* pB = g_Bh + (size_t)n0 * C_DIM;

    const int ldSeg = tid & 3;
    const int ldRow = tid >> 2;

    const uint32_t aRow = (uint32_t)(wm * 32 + (lane & 15)) * ROWB2
                        + (uint32_t)(lane >> 4) * 16;
    const uint32_t bRow = (uint32_t)(wn * 64 + ((lane >> 4) << 3) + (lane & 7)) * ROWB2
                        + (uint32_t)((lane >> 3) & 1) * 16;

    float acc[2][8][4];
#pragma unroll
    for (int i = 0; i < 2; ++i)
#pragma unroll
        for (int j = 0; j < 8; ++j)
#pragma unroll
            for (int q = 0; q < 4; ++q) acc[i][j][q] = 0.f;

    auto load_chunk = [&](int c, int st) {
        const uint32_t sb = su + st * STG2;
        const int kb = c * 32 + ldSeg * 8;
#pragma unroll
        for (int p = 0; p < 2; ++p) {
            int row = p * 64 + ldRow;
            uint32_t so = (uint32_t)row * ROWB2 + (uint32_t)ldSeg * 16;
            size_t gi = (size_t)row * C_DIM + kb;
            cp16(sb + so,        pA + gi);
            cp16(sb + ARR2 + so, pB + gi);
        }
    };

    load_chunk(0, 0); CP_COMMIT();
    load_chunk(1, 1); CP_COMMIT();
    load_chunk(2, 2); CP_COMMIT();

#pragma unroll 1
    for (int c = 0; c < 8; ++c) {
        CP_WAIT(2);                     // chunk c resident
        __syncthreads();                // all threads see stage c; frees stage (c-1)%4
        if (c + 3 < 8) load_chunk(c + 3, (c + 3) & 3);
        CP_COMMIT();                    // uniform group count (empty in tail)

        const uint32_t sb = su + (c & 3) * STG2;
        const uint32_t sA = sb;
        const uint32_t sB = sb + ARR2;

#pragma unroll
        for (int ks = 0; ks < 2; ++ks) {
            uint32_t ah[2][4];
#pragma unroll
            for (int mt = 0; mt < 2; ++mt) {
                uint32_t ao = aRow + (uint32_t)mt * (16 * ROWB2) + (uint32_t)ks * 32;
                LDSM_X4(ah[mt], sA + ao);
            }
#pragma unroll
            for (int np = 0; np < 4; ++np) {
                uint32_t bo = bRow + (uint32_t)np * (16 * ROWB2) + (uint32_t)ks * 32;
                uint32_t bh[4];
                LDSM_X4(bh, sB + bo);
#pragma unroll
                for (int half = 0; half < 2; ++half) {
                    int nt = np * 2 + half;
                    MMA_F16(acc[0][nt], ah[0], bh + half * 2);
                    MMA_F16(acc[1][nt], ah[1], bh + half * 2);
                }
            }
        }
    }

    // ---- epilogue: bias add + scatter to g_qkv[which][win][head][t][d] ----
#pragma unroll
    for (int nt = 0; nt < 8; ++nt) {
        const int n = n0 + wn * 64 + nt * 8 + (lane & 3) * 2;
        const float2 bv = *(const float2*)(bias + n);
        const int which = n >> 8;
        const int head  = (n >> 5) & 7;
        const int d     = n & 31;
        const size_t nbase = (size_t)which * QKV_STRIDE + (size_t)head * (NTOK * HD) + d;
#pragma unroll
        for (int mt = 0; mt < 2; ++mt) {
            const int mb = m0 + wm * 32 + mt * 16 + (lane >> 2);
#pragma unroll
            for (int h = 0; h < 2; ++h) {
                const int m   = mb + h * 8;
                const int win = m >> 6;
                const int t   = m & 63;
                float2 v;
                v.x = acc[mt][nt][h * 2 + 0] + bv.x;
                v.y = acc[mt][nt][h * 2 + 1] + bv.y;
                *(float2*)(g_qkv + nbase + ((size_t)win * (HEADS * NTOK * HD) + (size_t)t * HD)) = v;
            }
        }
    }
}

// ---------------------------------------------------------------------------
// K2: fp16 HMMA attention. grid = (2048, 8), 128 threads (4 warps).
// Q/K/V fp16 in smem; S and P in MMA fragments; fp32 register softmax.
// ---------------------------------------------------------------------------
#define ASTRIDE 80
#define AQ 0
#define AK 5120
#define AV 10240

__global__ void __launch_bounds__(128)
attn_kernel(const float* __restrict__ table,
            float* __restrict__ out)
{
    __shared__ __align__(16) char smr[15360];
    __shared__ float biasS[225];
    __shared__ int   regS[64];

    const int win  = blockIdx.x;
    const int head = blockIdx.y;
    const int b  = win >> 6;
    const int wy = (win >> 3) & 7;
    const int wx = win & 7;

    const int tid  = threadIdx.x;
    const int lane = tid & 31;
    const int wid  = tid >> 5;
    const uint32_t sb = smem_u32(smr);

    const float* qb = g_qkv + (((size_t)win * HEADS + head) << 11);
    const float* kb = qb + QKV_STRIDE;
    const float* vb = qb + 2 * QKV_STRIDE;

    {
        auto load_cvt = [&](const float* src, int off, float scale) {
#pragma unroll
            for (int it = 0; it < 8; ++it) {
                int idx2 = it * 128 + tid;
                int t  = idx2 >> 4;
                int dp = idx2 & 15;
                float2 v = ((const float2*)src)[idx2];
                *(uint32_t*)(smr + off + t * ASTRIDE + dp * 4) = pack2h(v.x * scale, v.y * scale);
            }
        };
        load_cvt(qb, AQ, SCALE);
        load_cvt(kb, AK, 1.0f);
        load_cvt(vb, AV, 1.0f);
    }
    for (int i = tid; i < 225; i += 128) biasS[i] = table[i * 8 + head];
    if (tid < 64) {
        int yi = tid >> 3, xi = tid & 7;
        int h = wy * 8 + yi, w = wx * 8 + xi;
        int rh = (h < 56) ? 0 : ((h < 60) ? 1 : 2);
        int rw = (w < 56) ? 0 : ((w < 60) ? 1 : 2);
        regS[tid] = rh * 3 + rw;
    }
    __syncthreads();

    const int m0 = wid * 16;

    float accS[8][4];
#pragma unroll
    for (int i = 0; i < 8; ++i)
#pragma unroll
        for (int q = 0; q < 4; ++q) accS[i][q] = 0.f;

    const uint32_t aoff = (uint32_t)(m0 + (lane & 15)) * ASTRIDE + (uint32_t)(lane >> 4) * 16;
    const uint32_t koff = (uint32_t)(((lane >> 4) << 3) + (lane & 7)) * ASTRIDE
                        + (uint32_t)((lane >> 3) & 1) * 16;

#pragma unroll
    for (int kt = 0; kt < 2; ++kt) {
        uint32_t qf[4];
        LDSM_X4(qf, sb + AQ + aoff + kt * 32);
#pragma unroll
        for (int np = 0; np < 4; ++np) {
            uint32_t kf[4];
            LDSM_X4(kf, sb + AK + koff + (uint32_t)np * (16 * ASTRIDE) + kt * 32);
#pragma unroll
            for (int half = 0; half < 2; ++half)
                MMA_F16(accS[np * 2 + half], qf, kf + half * 2);
        }
    }

    const int r0 = m0 + (lane >> 2);
    const int r1 = r0 + 8;
    const int yi0 = r0 >> 3, xi0 = r0 & 7, rg0 = regS[r0];
    const int yi1 = r1 >> 3, xi1 = r1 & 7, rg1 = regS[r1];
#pragma unroll
    for (int nt = 0; nt < 8; ++nt) {
#pragma unroll
        for (int e = 0; e < 2; ++e) {
            int s  = nt * 8 + (lane & 3) * 2 + e;
            int ys = s >> 3, xs = s & 7;
            int rs = regS[s];
            accS[nt][e]     += biasS[(yi0 - ys + 7) * 15 + (xi0 - xs + 7)]
                             + (rs != rg0 ? -100.0f : 0.0f);
            accS[nt][2 + e] += biasS[(yi1 - ys + 7) * 15 + (xi1 - xs + 7)]
                             + (rs != rg1 ? -100.0f : 0.0f);
        }
    }

    {
        float mx0 = -1e30f, mx1 = -1e30f;
#pragma unroll
        for (int nt = 0; nt < 8; ++nt) {
            mx0 = fmaxf(mx0, fmaxf(accS[nt][0], accS[nt][1]));
            mx1 = fmaxf(mx1, fmaxf(accS[nt][2], accS[nt][3]));
        }
#pragma unroll
        for (int o = 1; o < 4; o <<= 1) {
            mx0 = fmaxf(mx0, __shfl_xor_sync(0xFFFFFFFF, mx0, o));
            mx1 = fmaxf(mx1, __shfl_xor_sync(0xFFFFFFFF, mx1, o));
        }
        float sum0 = 0.f, sum1 = 0.f;
#pragma unroll
        for (int nt = 0; nt < 8; ++nt) {
            accS[nt][0] = __expf(accS[nt][0] - mx0);
            accS[nt][1] = __expf(accS[nt][1] - mx0);
            accS[nt][2] = __expf(accS[nt][2] - mx1);
            accS[nt][3] = __expf(accS[nt][3] - mx1);
            sum0 += accS[nt][0] + accS[nt][1];
            sum1 += accS[nt][2] + accS[nt][3];
        }
#pragma unroll
        for (int o = 1; o < 4; o <<= 1) {
            sum0 += __shfl_xor_sync(0xFFFFFFFF, sum0, o);
            sum1 += __shfl_xor_sync(0xFFFFFFFF, sum1, o);
        }
        float inv0 = 1.0f / sum0, inv1 = 1.0f / sum1;
#pragma unroll
        for (int nt = 0; nt < 8; ++nt) {
            accS[nt][0] *= inv0; accS[nt][1] *= inv0;
            accS[nt][2] *= inv1; accS[nt][3] *= inv1;
        }
    }

    // pack P to fp16 A-fragments
    uint32_t pf[4][4];
#pragma unroll
    for (int kt = 0; kt < 4; ++kt) {
        pf[kt][0] = pack2h(accS[2 * kt][0],     accS[2 * kt][1]);
        pf[kt][1] = pack2h(accS[2 * kt][2],     accS[2 * kt][3]);
        pf[kt][2] = pack2h(accS[2 * kt + 1][0], accS[2 * kt + 1][1]);
        pf[kt][3] = pack2h(accS[2 * kt + 1][2], accS[2 * kt + 1][3]);
    }

    float accO[4][4];
#pragma unroll
    for (int i = 0; i < 4; ++i)
#pragma unroll
        for (int q = 0; q < 4; ++q) accO[i][q] = 0.f;

    const uint32_t vrow = (uint32_t)((lane & 7) + ((lane >> 3) & 1) * 8) * ASTRIDE
                        + (uint32_t)((lane >> 4) << 3) * 2;
#pragma unroll
    for (int kt = 0; kt < 4; ++kt) {
#pragma unroll
        for (int np = 0; np < 2; ++np) {
            uint32_t vf[4];
            LDSM_X4T(vf, sb + AV + vrow + (uint32_t)kt * (16 * ASTRIDE) + (uint32_t)np * 32);
#pragma unroll
            for (int half = 0; half < 2; ++half)
                MMA_F16(accO[np * 2 + half], pf[kt], vf + half * 2);
        }
    }

    __syncthreads();
    float* Osm = (float*)smr;
#pragma unroll
    for (int nt = 0; nt < 4; ++nt) {
        int d0 = nt * 8 + (lane & 3) * 2;
        Osm[r0 * 33 + d0]     = accO[nt][0];
        Osm[r0 * 33 + d0 + 1] = accO[nt][1];
        Osm[r1 * 33 + d0]     = accO[nt][2];
        Osm[r1 * 33 + d0 + 1] = accO[nt][3];
    }
    __syncthreads();

    size_t obase = ((size_t)b << 20) + ((size_t)head << 17);
#pragma unroll
    for (int it = 0; it < 16; ++it) {
        int idx = it * 128 + tid;
        int d = idx >> 6, t = idx & 63;
        int yi = t >> 3, xi = t & 7;
        int gh = (wy * 8 + yi + 4) & 63;
        int gw = (wx * 8 + xi + 4) & 63;
        out[obase + ((size_t)d << 12) + gh * 64 + gw] = Osm[t * 33 + d];
    }
}

// ---------------------------------------------------------------------------
extern "C" void kernel_launch(void* const* d_in, const int* in_sizes, int n_in,
                              void* d_out, int out_size)
{
    (void)in_sizes; (void)n_in; (void)out_size;
    const float* x    = (const float*)d_in[0];
    const float* qkvw = (const float*)d_in[1];
    const float* qkvb = (const float*)d_in[2];
    const float* tbl  = (const float*)d_in[3];
    float* out = (float*)d_out;

    cudaFuncSetAttribute(qkv_mma_kernel,
                         cudaFuncAttributeMaxDynamicSharedMemorySize, NSTG * STG2);

    gather_split_kernel<<<NWIN_TOT, 256>>>(x);
    transW_kernel<<<192, 256>>>(qkvw);
    qkv_mma_kernel<<<dim3(6, 1024), 256, NSTG * STG2>>>(qkvb);
    attn_kernel<<<dim3(NWIN_TOT, HEADS), 128>>>(tbl, out);
}

// round 9
// speedup vs baseline: 4.1800x; 1.0768x over previous
#include <cuda_runtime.h>
#include <cuda_bf16.h>
#include <cuda_fp16.h>
#include <cstdint>

// ---------------------------------------------------------------------------
// WindowAttention (Swin shifted-window attention).
//   B=32, DIM=256, H=W=64, WIN=8, SHIFT=4, HEADS=8, HEAD_DIM=32, N=64
// R9: qkv scratch stored as fp16 (Q pre-scaled) straight from GEMM epilogue.
//     Attention smem filled by raw cp.async (no conversion ALU).
//     GEMM: fp16 HMMA, 4-stage cp.async pipeline, 2 CTAs/SM.
// ---------------------------------------------------------------------------

#define NWIN_TOT   2048
#define M_TOT      131072
#define C_DIM      256
#define N3C        768
#define HEADS      8
#define HD         32
#define NTOK       64
#define SCALE      0.17677669529663687f

__device__ __half g_Ah[(size_t)M_TOT * C_DIM];
__device__ __half g_Bh[(size_t)N3C * C_DIM];
__device__ __half g_qkvh[(size_t)3 * NWIN_TOT * HEADS * NTOK * HD];

#define QKV_STRIDE ((size_t)NWIN_TOT * HEADS * NTOK * HD)

// ------------------------------ helpers -----------------------------------
__device__ __forceinline__ uint32_t smem_u32(const void* p) {
    uint32_t a;
    asm("{ .reg .u64 t; cvta.to.shared.u64 t, %1; cvt.u32.u64 %0, t; }"
        : "=r"(a) : "l"(p));
    return a;
}

__device__ __forceinline__ void cp16(uint32_t saddr, const void* g) {
    asm volatile("cp.async.cg.shared.global [%0], [%1], 16;" :: "r"(saddr), "l"(g));
}
#define CP_COMMIT()  asm volatile("cp.async.commit_group;" ::: "memory")
#define CP_WAIT(N)   asm volatile("cp.async.wait_group %0;" :: "n"(N) : "memory")

#define LDSM_X4(r, addr) \
    asm volatile("ldmatrix.sync.aligned.m8n8.x4.shared.b16 {%0,%1,%2,%3}, [%4];" \
        : "=r"((r)[0]), "=r"((r)[1]), "=r"((r)[2]), "=r"((r)[3]) : "r"(addr))
#define LDSM_X4T(r, addr) \
    asm volatile("ldmatrix.sync.aligned.m8n8.x4.trans.shared.b16 {%0,%1,%2,%3}, [%4];" \
        : "=r"((r)[0]), "=r"((r)[1]), "=r"((r)[2]), "=r"((r)[3]) : "r"(addr))

#define MMA_F16(d, a, b) \
    asm volatile("mma.sync.aligned.m16n8k16.row.col.f32.f16.f16.f32 " \
        "{%0,%1,%2,%3}, {%4,%5,%6,%7}, {%8,%9}, {%0,%1,%2,%3};" \
        : "+f"((d)[0]), "+f"((d)[1]), "+f"((d)[2]), "+f"((d)[3]) \
        : "r"((a)[0]), "r"((a)[1]), "r"((a)[2]), "r"((a)[3]), \
          "r"((b)[0]), "r"((b)[1]))

__device__ __forceinline__ uint32_t pack2h(float x, float y)
{
    __half2 a = __floats2half2_rn(x, y);
    return *(uint32_t*)&a;
}
__device__ __forceinline__ uint2 pack4h(float v0, float v1, float v2, float v3)
{
    uint2 r;
    r.x = pack2h(v0, v1);
    r.y = pack2h(v2, v3);
    return r;
}

// ---------------------------------------------------------------------------
// K0: gather + roll + window partition + fp32->fp16
// ---------------------------------------------------------------------------
__global__ void __launch_bounds__(256)
gather_split_kernel(const float* __restrict__ x)
{
    __shared__ float sm[64 * 65];
    const int blk = blockIdx.x;
    const int b  = blk >> 6;
    const int wy = (blk >> 3) & 7;
    const int wx = blk & 7;
    const int tid = threadIdx.x;

    uint2* dh = (uint2*)g_Ah + (size_t)blk * 4096;
    const float* xb = x + ((size_t)b << 20);

#pragma unroll 1
    for (int cc = 0; cc < 4; ++cc) {
#pragma unroll
        for (int it = 0; it < 16; ++it) {
            int idx = it * 256 + tid;
            int cl = idx >> 6;
            int t  = idx & 63;
            int i = t >> 3, j = t & 7;
            int gh = (wy * 8 + i + 4) & 63;
            int gw = (wx * 8 + j + 4) & 63;
            sm[t * 65 + cl] = xb[((size_t)(cc * 64 + cl) << 12) + gh * 64 + gw];
        }
        __syncthreads();
#pragma unroll
        for (int it = 0; it < 4; ++it) {
            int idx = it * 256 + tid;
            int t  = idx >> 4;
            int cq = idx & 15;
            const float* s = sm + t * 65 + cq * 4;
            dh[t * 64 + cc * 16 + cq] = pack4h(s[0], s[1], s[2], s[3]);
        }
        __syncthreads();
    }
}

// ---------------------------------------------------------------------------
// K0b: transpose qkv_w [K=256][N=768] -> B [N][K] fp16
// ---------------------------------------------------------------------------
__global__ void __launch_bounds__(256)
transW_kernel(const float* __restrict__ W)
{
    int g = blockIdx.x * 256 + threadIdx.x;
    int n = g >> 6;
    int k4 = (g & 63) * 4;
    float v[4];
#pragma unroll
    for (int r = 0; r < 4; ++r) v[r] = W[(size_t)(k4 + r) * N3C + n];
    ((uint2*)g_Bh)[(size_t)n * 64 + (k4 >> 2)] = pack4h(v[0], v[1], v[2], v[3]);
}

// ---------------------------------------------------------------------------
// K1: fp16 HMMA QKV GEMM. grid = (6, 1024), 256 threads (8 warps 4x2).
// Tile 128x128, K=256 in 8 chunks of 32, 4-stage pipeline, 2 CTAs/SM.
// Epilogue: bias add (+SCALE for Q), pack fp16, scatter to g_qkvh.
// ---------------------------------------------------------------------------
#define ROWB2 80
#define ARR2  (128 * ROWB2)
#define STG2  (2 * ARR2)
#define NSTG  4

__global__ void __launch_bounds__(256, 2)
qkv_mma_kernel(const float* __restrict__ bias)
{
    extern __shared__ __align__(128) char dsm[];
    const uint32_t su = smem_u32(dsm);

    const int tid  = threadIdx.x;
    const int lane = tid & 31;
    const int wid  = tid >> 5;
    const int wm   = wid >> 1;
    const int wn   = wid & 1;
    const int n0   = blockIdx.x * 128;
    const int m0   = blockIdx.y * 128;

    const __half* pA = g_Ah + (size_t)m0 * C_DIM;
    const __half* pB = g_Bh + (size_t)n0 * C_DIM;

    const int ldSeg = tid & 3;
    const int ldRow = tid >> 2;

    const uint32_t aRow = (uint32_t)(wm * 32 + (lane & 15)) * ROWB2
                        + (uint32_t)(lane >> 4) * 16;
    const uint32_t bRow = (uint32_t)(wn * 64 + ((lane >> 4) << 3) + (lane & 7)) * ROWB2
                        + (uint32_t)((lane >> 3) & 1) * 16;

    float acc[2][8][4];
#pragma unroll
    for (int i = 0; i < 2; ++i)
#pragma unroll
        for (int j = 0; j < 8; ++j)
#pragma unroll
            for (int q = 0; q < 4; ++q) acc[i][j][q] = 0.f;

    auto load_chunk = [&](int c, int st) {
        const uint32_t sb = su + st * STG2;
        const int kb = c * 32 + ldSeg * 8;
#pragma unroll
        for (int p = 0; p < 2; ++p) {
            int row = p * 64 + ldRow;
            uint32_t so = (uint32_t)row * ROWB2 + (uint32_t)ldSeg * 16;
            size_t gi = (size_t)row * C_DIM + kb;
            cp16(sb + so,        pA + gi);
            cp16(sb + ARR2 + so, pB + gi);
        }
    };

    load_chunk(0, 0); CP_COMMIT();
    load_chunk(1, 1); CP_COMMIT();
    load_chunk(2, 2); CP_COMMIT();

#pragma unroll 1
    for (int c = 0; c < 8; ++c) {
        CP_WAIT(2);
        __syncthreads();
        if (c + 3 < 8) load_chunk(c + 3, (c + 3) & 3);
        CP_COMMIT();

        const uint32_t sb = su + (c & 3) * STG2;
        const uint32_t sA = sb;
        const uint32_t sB = sb + ARR2;

#pragma unroll
        for (int ks = 0; ks < 2; ++ks) {
            uint32_t ah[2][4];
#pragma unroll
            for (int mt = 0; mt < 2; ++mt) {
                uint32_t ao = aRow + (uint32_t)mt * (16 * ROWB2) + (uint32_t)ks * 32;
                LDSM_X4(ah[mt], sA + ao);
            }
#pragma unroll
            for (int np = 0; np < 4; ++np) {
                uint32_t bo = bRow + (uint32_t)np * (16 * ROWB2) + (uint32_t)ks * 32;
                uint32_t bh[4];
                LDSM_X4(bh, sB + bo);
#pragma unroll
                for (int half = 0; half < 2; ++half) {
                    int nt = np * 2 + half;
                    MMA_F16(acc[0][nt], ah[0], bh + half * 2);
                    MMA_F16(acc[1][nt], ah[1], bh + half * 2);
                }
            }
        }
    }

    // ---- epilogue: bias (+SCALE for Q), fp16 pack, scatter to g_qkvh ----
#pragma unroll
    for (int nt = 0; nt < 8; ++nt) {
        const int n = n0 + wn * 64 + nt * 8 + (lane & 3) * 2;
        const float2 bv = *(const float2*)(bias + n);
        const int which = n >> 8;
        const int head  = (n >> 5) & 7;
        const int d     = n & 31;
        const float scl = (which == 0) ? SCALE : 1.0f;
        const size_t nbase = (size_t)which * QKV_STRIDE + (size_t)head * (NTOK * HD) + d;
#pragma unroll
        for (int mt = 0; mt < 2; ++mt) {
            const int mb = m0 + wm * 32 + mt * 16 + (lane >> 2);
#pragma unroll
            for (int h = 0; h < 2; ++h) {
                const int m   = mb + h * 8;
                const int win = m >> 6;
                const int t   = m & 63;
                uint32_t pk = pack2h((acc[mt][nt][h * 2 + 0] + bv.x) * scl,
                                     (acc[mt][nt][h * 2 + 1] + bv.y) * scl);
                *(uint32_t*)(g_qkvh + nbase
                    + ((size_t)win * (HEADS * NTOK * HD) + (size_t)t * HD)) = pk;
            }
        }
    }
}

// ---------------------------------------------------------------------------
// K2: fp16 HMMA attention. grid = (2048, 8), 128 threads (4 warps).
// Q/K/V fp16 in smem via raw cp.async; fp32 register softmax.
// ---------------------------------------------------------------------------
#define ASTRIDE 80
#define AQ 0
#define AK 5120
#define AV 10240

__global__ void __launch_bounds__(128)
attn_kernel(const float* __restrict__ table,
            float* __restrict__ out)
{
    __shared__ __align__(16) char smr[15360];
    __shared__ float biasS[225];
    __shared__ int   regS[64];

    const int win  = blockIdx.x;
    const int head = blockIdx.y;
    const int b  = win >> 6;
    const int wy = (win >> 3) & 7;
    const int wx = win & 7;

    const int tid  = threadIdx.x;
    const int lane = tid & 31;
    const int wid  = tid >> 5;
    const uint32_t sb = smem_u32(smr);

    const __half* qb = g_qkvh + (((size_t)win * HEADS + head) << 11);
    const __half* kb = qb + QKV_STRIDE;
    const __half* vb = qb + 2 * QKV_STRIDE;

    // raw async copy: 64 rows x 64B per array, stride 80
#pragma unroll
    for (int it = 0; it < 2; ++it) {
        int idx = it * 128 + tid;            // 0..255
        int t = idx >> 2, seg = idx & 3;
        uint32_t dofs = (uint32_t)t * ASTRIDE + (uint32_t)seg * 16;
        size_t gofs = (size_t)t * 32 + seg * 8;
        cp16(sb + AQ + dofs, qb + gofs);
        cp16(sb + AK + dofs, kb + gofs);
        cp16(sb + AV + dofs, vb + gofs);
    }
    CP_COMMIT();

    for (int i = tid; i < 225; i += 128) biasS[i] = table[i * 8 + head];
    if (tid < 64) {
        int yi = tid >> 3, xi = tid & 7;
        int h = wy * 8 + yi, w = wx * 8 + xi;
        int rh = (h < 56) ? 0 : ((h < 60) ? 1 : 2);
        int rw = (w < 56) ? 0 : ((w < 60) ? 1 : 2);
        regS[tid] = rh * 3 + rw;
    }
    CP_WAIT(0);
    __syncthreads();

    const int m0 = wid * 16;

    float accS[8][4];
#pragma unroll
    for (int i = 0; i < 8; ++i)
#pragma unroll
        for (int q = 0; q < 4; ++q) accS[i][q] = 0.f;

    const uint32_t aoff = (uint32_t)(m0 + (lane & 15)) * ASTRIDE + (uint32_t)(lane >> 4) * 16;
    const uint32_t koff = (uint32_t)(((lane >> 4) << 3) + (lane & 7)) * ASTRIDE
                        + (uint32_t)((lane >> 3) & 1) * 16;

#pragma unroll
    for (int kt = 0; kt < 2; ++kt) {
        uint32_t qf[4];
        LDSM_X4(qf, sb + AQ + aoff + kt * 32);
#pragma unroll
        for (int np = 0; np < 4; ++np) {
            uint32_t kf[4];
            LDSM_X4(kf, sb + AK + koff + (uint32_t)np * (16 * ASTRIDE) + kt * 32);
#pragma unroll
            for (int half = 0; half < 2; ++half)
                MMA_F16(accS[np * 2 + half], qf, kf + half * 2);
        }
    }

    const int r0 = m0 + (lane >> 2);
    const int r1 = r0 + 8;
    const int yi0 = r0 >> 3, xi0 = r0 & 7, rg0 = regS[r0];
    const int yi1 = r1 >> 3, xi1 = r1 & 7, rg1 = regS[r1];
#pragma unroll
    for (int nt = 0; nt < 8; ++nt) {
#pragma unroll
        for (int e = 0; e < 2; ++e) {
            int s  = nt * 8 + (lane & 3) * 2 + e;
            int ys = s >> 3, xs = s & 7;
            int rs = regS[s];
            accS[nt][e]     += biasS[(yi0 - ys + 7) * 15 + (xi0 - xs + 7)]
                             + (rs != rg0 ? -100.0f : 0.0f);
            accS[nt][2 + e] += biasS[(yi1 - ys + 7) * 15 + (xi1 - xs + 7)]
                             + (rs != rg1 ? -100.0f : 0.0f);
        }
    }

    {
        float mx0 = -1e30f, mx1 = -1e30f;
#pragma unroll
        for (int nt = 0; nt < 8; ++nt) {
            mx0 = fmaxf(mx0, fmaxf(accS[nt][0], accS[nt][1]));
            mx1 = fmaxf(mx1, fmaxf(accS[nt][2], accS[nt][3]));
        }
#pragma unroll
        for (int o = 1; o < 4; o <<= 1) {
            mx0 = fmaxf(mx0, __shfl_xor_sync(0xFFFFFFFF, mx0, o));
            mx1 = fmaxf(mx1, __shfl_xor_sync(0xFFFFFFFF, mx1, o));
        }
        float sum0 = 0.f, sum1 = 0.f;
#pragma unroll
        for (int nt = 0; nt < 8; ++nt) {
            accS[nt][0] = __expf(accS[nt][0] - mx0);
            accS[nt][1] = __expf(accS[nt][1] - mx0);
            accS[nt][2] = __expf(accS[nt][2] - mx1);
            accS[nt][3] = __expf(accS[nt][3] - mx1);
            sum0 += accS[nt][0] + accS[nt][1];
            sum1 += accS[nt][2] + accS[nt][3];
        }
#pragma unroll
        for (int o = 1; o < 4; o <<= 1) {
            sum0 += __shfl_xor_sync(0xFFFFFFFF, sum0, o);
            sum1 += __shfl_xor_sync(0xFFFFFFFF, sum1, o);
        }
        float inv0 = 1.0f / sum0, inv1 = 1.0f / sum1;
#pragma unroll
        for (int nt = 0; nt < 8; ++nt) {
            accS[nt][0] *= inv0; accS[nt][1] *= inv0;
            accS[nt][2] *= inv1; accS[nt][3] *= inv1;
        }
    }

    uint32_t pf[4][4];
#pragma unroll
    for (int kt = 0; kt < 4; ++kt) {
        pf[kt][0] = pack2h(accS[2 * kt][0],     accS[2 * kt][1]);
        pf[kt][1] = pack2h(accS[2 * kt][2],     accS[2 * kt][3]);
        pf[kt][2] = pack2h(accS[2 * kt + 1][0], accS[2 * kt + 1][1]);
        pf[kt][3] = pack2h(accS[2 * kt + 1][2], accS[2 * kt + 1][3]);
    }

    float accO[4][4];
#pragma unroll
    for (int i = 0; i < 4; ++i)
#pragma unroll
        for (int q = 0; q < 4; ++q) accO[i][q] = 0.f;

    const uint32_t vrow = (uint32_t)((lane & 7) + ((lane >> 3) & 1) * 8) * ASTRIDE
                        + (uint32_t)((lane >> 4) << 3) * 2;
#pragma unroll
    for (int kt = 0; kt < 4; ++kt) {
#pragma unroll
        for (int np = 0; np < 2; ++np) {
            uint32_t vf[4];
            LDSM_X4T(vf, sb + AV + vrow + (uint32_t)kt * (16 * ASTRIDE) + (uint32_t)np * 32);
#pragma unroll
            for (int half = 0; half < 2; ++half)
                MMA_F16(accO[np * 2 + half], pf[kt], vf + half * 2);
        }
    }

    __syncthreads();
    float* Osm = (float*)smr;
#pragma unroll
    for (int nt = 0; nt < 4; ++nt) {
        int d0 = nt * 8 + (lane & 3) * 2;
        Osm[r0 * 33 + d0]     = accO[nt][0];
        Osm[r0 * 33 + d0 + 1] = accO[nt][1];
        Osm[r1 * 33 + d0]     = accO[nt][2];
        Osm[r1 * 33 + d0 + 1] = accO[nt][3];
    }
    __syncthreads();

    size_t obase = ((size_t)b << 20) + ((size_t)head << 17);
#pragma unroll
    for (int it = 0; it < 16; ++it) {
        int idx = it * 128 + tid;
        int d = idx >> 6, t = idx & 63;
        int yi = t >> 3, xi = t & 7;
        int gh = (wy * 8 + yi + 4) & 63;
        int gw = (wx * 8 + xi + 4) & 63;
        out[obase + ((size_t)d << 12) + gh * 64 + gw] = Osm[t * 33 + d];
    }
}

// ---------------------------------------------------------------------------
extern "C" void kernel_launch(void* const* d_in, const int* in_sizes, int n_in,
                              void* d_out, int out_size)
{
    (void)in_sizes; (void)n_in; (void)out_size;
    const float* x    = (const float*)d_in[0];
    const float* qkvw = (const float*)d_in[1];
    const float* qkvb = (const float*)d_in[2];
    const float* tbl  = (const float*)d_in[3];
    float* out = (float*)d_out;

    cudaFuncSetAttribute(qkv_mma_kernel,
                         cudaFuncAttributeMaxDynamicSharedMemorySize, NSTG * STG2);

    gather_split_kernel<<<NWIN_TOT, 256>>>(x);
    transW_kernel<<<192, 256>>>(qkvw);
    qkv_mma_kernel<<<dim3(6, 1024), 256, NSTG * STG2>>>(qkvb);
    attn_kernel<<<dim3(NWIN_TOT, HEADS), 128>>>(tbl, out);
}

// round 10
// speedup vs baseline: 4.6003x; 1.1006x over previous
#include <cuda_runtime.h>
#include <cuda_bf16.h>
#include <cuda_fp16.h>
#include <cstdint>

// ---------------------------------------------------------------------------
// WindowAttention (Swin shifted-window attention).
//   B=32, DIM=256, H=W=64, WIN=8, SHIFT=4, HEADS=8, HEAD_DIM=32, N=64
// R10: GEMM mainloop with NO __syncthreads — 4-stage mbarrier full/empty ring
//      (cp.async.mbarrier.arrive.noinc). Warps drift freely; tensor pipe fed
//      across chunk boundaries. qkv fp16 scratch (R9), fp16 HMMA attention.
// ---------------------------------------------------------------------------

#define NWIN_TOT   2048
#define M_TOT      131072
#define C_DIM      256
#define N3C        768
#define HEADS      8
#define HD         32
#define NTOK       64
#define SCALE      0.17677669529663687f

__device__ __half g_Ah[(size_t)M_TOT * C_DIM];
__device__ __half g_Bh[(size_t)N3C * C_DIM];
__device__ __half g_qkvh[(size_t)3 * NWIN_TOT * HEADS * NTOK * HD];

#define QKV_STRIDE ((size_t)NWIN_TOT * HEADS * NTOK * HD)

// ------------------------------ helpers -----------------------------------
__device__ __forceinline__ uint32_t smem_u32(const void* p) {
    uint32_t a;
    asm("{ .reg .u64 t; cvta.to.shared.u64 t, %1; cvt.u32.u64 %0, t; }"
        : "=r"(a) : "l"(p));
    return a;
}

__device__ __forceinline__ void cp16(uint32_t saddr, const void* g) {
    asm volatile("cp.async.cg.shared.global [%0], [%1], 16;" :: "r"(saddr), "l"(g));
}
#define CP_COMMIT()  asm volatile("cp.async.commit_group;" ::: "memory")
#define CP_WAIT(N)   asm volatile("cp.async.wait_group %0;" :: "n"(N) : "memory")

#define MBARRIER_INIT(a, cnt) \
    asm volatile("mbarrier.init.shared.b64 [%0], %1;" :: "r"((uint32_t)(a)), "r"((uint32_t)(cnt)) : "memory")
#define MBARRIER_ARRIVE(a) \
    asm volatile("mbarrier.arrive.shared.b64 _, [%0];" :: "r"((uint32_t)(a)) : "memory")
#define CP_MBAR_ARRIVE(a) \
    asm volatile("cp.async.mbarrier.arrive.noinc.shared.b64 [%0];" :: "r"((uint32_t)(a)) : "memory")

#define MBARRIER_WAIT_PARITY(a, par) do { \
    uint32_t _m = (uint32_t)(a); uint32_t _p = (uint32_t)(par); uint32_t _d; \
    asm volatile("{\n\t.reg .pred p;\n\t" \
        "mbarrier.try_wait.parity.acquire.cta.shared::cta.b64 p, [%1], %2;\n\t" \
        "selp.b32 %0, 1, 0, p;\n\t}" : "=r"(_d) : "r"(_m), "r"(_p) : "memory"); \
    if (!_d) { \
        asm volatile("{\n\t.reg .pred P1;\n\t" \
            "WL_%=:\n\t" \
            "mbarrier.try_wait.parity.acquire.cta.shared::cta.b64 P1, [%0], %1, 0x989680;\n\t" \
            "@P1 bra.uni WD_%=;\n\t" \
            "bra.uni WL_%=;\n\t" \
            "WD_%=:\n\t}" :: "r"(_m), "r"(_p) : "memory"); \
    } \
} while (0)

#define LDSM_X4(r, addr) \
    asm volatile("ldmatrix.sync.aligned.m8n8.x4.shared.b16 {%0,%1,%2,%3}, [%4];" \
        : "=r"((r)[0]), "=r"((r)[1]), "=r"((r)[2]), "=r"((r)[3]) : "r"(addr))
#define LDSM_X4T(r, addr) \
    asm volatile("ldmatrix.sync.aligned.m8n8.x4.trans.shared.b16 {%0,%1,%2,%3}, [%4];" \
        : "=r"((r)[0]), "=r"((r)[1]), "=r"((r)[2]), "=r"((r)[3]) : "r"(addr))

#define MMA_F16(d, a, b) \
    asm volatile("mma.sync.aligned.m16n8k16.row.col.f32.f16.f16.f32 " \
        "{%0,%1,%2,%3}, {%4,%5,%6,%7}, {%8,%9}, {%0,%1,%2,%3};" \
        : "+f"((d)[0]), "+f"((d)[1]), "+f"((d)[2]), "+f"((d)[3]) \
        : "r"((a)[0]), "r"((a)[1]), "r"((a)[2]), "r"((a)[3]), \
          "r"((b)[0]), "r"((b)[1]))

__device__ __forceinline__ uint32_t pack2h(float x, float y)
{
    __half2 a = __floats2half2_rn(x, y);
    return *(uint32_t*)&a;
}
__device__ __forceinline__ uint2 pack4h(float v0, float v1, float v2, float v3)
{
    uint2 r;
    r.x = pack2h(v0, v1);
    r.y = pack2h(v2, v3);
    return r;
}

// ---------------------------------------------------------------------------
// K0: gather + roll + window partition + fp32->fp16
// ---------------------------------------------------------------------------
__global__ void __launch_bounds__(256)
gather_split_kernel(const float* __restrict__ x)
{
    __shared__ float sm[64 * 65];
    const int blk = blockIdx.x;
    const int b  = blk >> 6;
    const int wy = (blk >> 3) & 7;
    const int wx = blk & 7;
    const int tid = threadIdx.x;

    uint2* dh = (uint2*)g_Ah + (size_t)blk * 4096;
    const float* xb = x + ((size_t)b << 20);

#pragma unroll 1
    for (int cc = 0; cc < 4; ++cc) {
#pragma unroll
        for (int it = 0; it < 16; ++it) {
            int idx = it * 256 + tid;
            int cl = idx >> 6;
            int t  = idx & 63;
            int i = t >> 3, j = t & 7;
            int gh = (wy * 8 + i + 4) & 63;
            int gw = (wx * 8 + j + 4) & 63;
            sm[t * 65 + cl] = xb[((size_t)(cc * 64 + cl) << 12) + gh * 64 + gw];
        }
        __syncthreads();
#pragma unroll
        for (int it = 0; it < 4; ++it) {
            int idx = it * 256 + tid;
            int t  = idx >> 4;
            int cq = idx & 15;
            const float* s = sm + t * 65 + cq * 4;
            dh[t * 64 + cc * 16 + cq] = pack4h(s[0], s[1], s[2], s[3]);
        }
        __syncthreads();
    }
}

// ---------------------------------------------------------------------------
// K0b: transpose qkv_w [K=256][N=768] -> B [N][K] fp16
// ---------------------------------------------------------------------------
__global__ void __launch_bounds__(256)
transW_kernel(const float* __restrict__ W)
{
    int g = blockIdx.x * 256 + threadIdx.x;
    int n = g >> 6;
    int k4 = (g & 63) * 4;
    float v[4];
#pragma unroll
    for (int r = 0; r < 4; ++r) v[r] = W[(size_t)(k4 + r) * N3C + n];
    ((uint2*)g_Bh)[(size_t)n * 64 + (k4 >> 2)] = pack4h(v[0], v[1], v[2], v[3]);
}

// ---------------------------------------------------------------------------
// K1: fp16 HMMA QKV GEMM, barrier-free mainloop via mbarrier ring.
// grid = (6, 1024), 256 threads (8 warps 4x2). Tile 128x128, K=256 in
// 8 chunks of 32, 4-stage ring, 2 CTAs/SM.
// Stage = 2 arrays * 128 rows * 80B = 20480B; 4 stages = 81920B.
// full[s]: 256 arrivals (cp.async.mbarrier.arrive.noinc per thread)
// empty[s]: 256 arrivals (each consumer thread after its chunk MMAs)
// ---------------------------------------------------------------------------
#define ROWB2 80
#define ARR2  (128 * ROWB2)
#define STG2  (2 * ARR2)
#define NSTG  4

__global__ void __launch_bounds__(256, 2)
qkv_mma_kernel(const float* __restrict__ bias)
{
    extern __shared__ __align__(128) char dsm[];
    __shared__ __align__(16) unsigned long long s_mb[2 * NSTG];
    const uint32_t su = smem_u32(dsm);
    const uint32_t mb = smem_u32(&s_mb[0]);
#define MB_FULL(s)  (mb + (uint32_t)(s) * 16u)
#define MB_EMPTY(s) (mb + (uint32_t)(s) * 16u + 8u)

    const int tid  = threadIdx.x;
    const int lane = tid & 31;
    const int wid  = tid >> 5;
    const int wm   = wid >> 1;
    const int wn   = wid & 1;
    const int n0   = blockIdx.x * 128;
    const int m0   = blockIdx.y * 128;

    const __half* pA = g_Ah + (size_t)m0 * C_DIM;
    const __half* pB = g_Bh + (size_t)n0 * C_DIM;

    const int ldSeg = tid & 3;
    const int ldRow = tid >> 2;

    const uint32_t aRow = (uint32_t)(wm * 32 + (lane & 15)) * ROWB2
                        + (uint32_t)(lane >> 4) * 16;
    const uint32_t bRow = (uint32_t)(wn * 64 + ((lane >> 4) << 3) + (lane & 7)) * ROWB2
                        + (uint32_t)((lane >> 3) & 1) * 16;

    if (tid == 0) {
#pragma unroll
        for (int s = 0; s < NSTG; ++s) {
            MBARRIER_INIT(MB_FULL(s), 256);
            MBARRIER_INIT(MB_EMPTY(s), 256);
        }
    }
    __syncthreads();          // the ONLY CTA-wide barrier

    float acc[2][8][4];
#pragma unroll
    for (int i = 0; i < 2; ++i)
#pragma unroll
        for (int j = 0; j < 8; ++j)
#pragma unroll
            for (int q = 0; q < 4; ++q) acc[i][j][q] = 0.f;

    // produce chunk c into stage st (after waiting empty at phase ep)
    auto produce = [&](int c, int st, int ep) {
        MBARRIER_WAIT_PARITY(MB_EMPTY(st), ep);
        const uint32_t sb = su + (uint32_t)st * STG2;
        const int kb = c * 32 + ldSeg * 8;
#pragma unroll
        for (int p = 0; p < 2; ++p) {
            int row = p * 64 + ldRow;
            uint32_t so = (uint32_t)row * ROWB2 + (uint32_t)ldSeg * 16;
            size_t gi = (size_t)row * C_DIM + kb;
            cp16(sb + so,        pA + gi);
            cp16(sb + ARR2 + so, pB + gi);
        }
        CP_MBAR_ARRIVE(MB_FULL(st));
    };

    // prologue: chunks 0..2 (fresh empty barriers pass at phase 1)
    produce(0, 0, 1);
    produce(1, 1, 1);
    produce(2, 2, 1);
    int pstage = 3, pphase = 1;
    int fstage = 0, fphase = 0;

#pragma unroll 1
    for (int c = 0; c < 8; ++c) {
        MBARRIER_WAIT_PARITY(MB_FULL(fstage), fphase);

        const uint32_t sb = su + (uint32_t)fstage * STG2;
        const uint32_t sA = sb;
        const uint32_t sB = sb + ARR2;

#pragma unroll
        for (int ks = 0; ks < 2; ++ks) {
            uint32_t ah[2][4];
#pragma unroll
            for (int mt = 0; mt < 2; ++mt) {
                uint32_t ao = aRow + (uint32_t)mt * (16 * ROWB2) + (uint32_t)ks * 32;
                LDSM_X4(ah[mt], sA + ao);
            }
#pragma unroll
            for (int np = 0; np < 4; ++np) {
                uint32_t bo = bRow + (uint32_t)np * (16 * ROWB2) + (uint32_t)ks * 32;
                uint32_t bh[4];
                LDSM_X4(bh, sB + bo);
#pragma unroll
                for (int half = 0; half < 2; ++half) {
                    int nt = np * 2 + half;
                    MMA_F16(acc[0][nt], ah[0], bh + half * 2);
                    MMA_F16(acc[1][nt], ah[1], bh + half * 2);
                }
            }
        }

        MBARRIER_ARRIVE(MB_EMPTY(fstage));
        if (c + 3 < 8) {
            produce(c + 3, pstage, pphase);
            if (++pstage == NSTG) { pstage = 0; pphase ^= 1; }
        }
        if (++fstage == NSTG) { fstage = 0; fphase ^= 1; }
    }

    // ---- epilogue: bias (+SCALE for Q), fp16 pack, scatter to g_qkvh ----
#pragma unroll
    for (int nt = 0; nt < 8; ++nt) {
        const int n = n0 + wn * 64 + nt * 8 + (lane & 3) * 2;
        const float2 bv = *(const float2*)(bias + n);
        const int which = n >> 8;
        const int head  = (n >> 5) & 7;
        const int d     = n & 31;
        const float scl = (which == 0) ? SCALE : 1.0f;
        const size_t nbase = (size_t)which * QKV_STRIDE + (size_t)head * (NTOK * HD) + d;
#pragma unroll
        for (int mt = 0; mt < 2; ++mt) {
            const int mb2 = m0 + wm * 32 + mt * 16 + (lane >> 2);
#pragma unroll
            for (int h = 0; h < 2; ++h) {
                const int m   = mb2 + h * 8;
                const int win = m >> 6;
                const int t   = m & 63;
                uint32_t pk = pack2h((acc[mt][nt][h * 2 + 0] + bv.x) * scl,
                                     (acc[mt][nt][h * 2 + 1] + bv.y) * scl);
                *(uint32_t*)(g_qkvh + nbase
                    + ((size_t)win * (HEADS * NTOK * HD) + (size_t)t * HD)) = pk;
            }
        }
    }
#undef MB_FULL
#undef MB_EMPTY
}

// ---------------------------------------------------------------------------
// K2: fp16 HMMA attention. grid = (2048, 8), 128 threads (4 warps).
// Q/K/V fp16 in smem via raw cp.async; fp32 register softmax.
// ---------------------------------------------------------------------------
#define ASTRIDE 80
#define AQ 0
#define AK 5120
#define AV 10240

__global__ void __launch_bounds__(128)
attn_kernel(const float* __restrict__ table,
            float* __restrict__ out)
{
    __shared__ __align__(16) char smr[15360];
    __shared__ float biasS[225];
    __shared__ int   regS[64];

    const int win  = blockIdx.x;
    const int head = blockIdx.y;
    const int b  = win >> 6;
    const int wy = (win >> 3) & 7;
    const int wx = win & 7;

    const int tid  = threadIdx.x;
    const int lane = tid & 31;
    const int wid  = tid >> 5;
    const uint32_t sb = smem_u32(smr);

    const __half* qb = g_qkvh + (((size_t)win * HEADS + head) << 11);
    const __half* kb = qb + QKV_STRIDE;
    const __half* vb = qb + 2 * QKV_STRIDE;

#pragma unroll
    for (int it = 0; it < 2; ++it) {
        int idx = it * 128 + tid;
        int t = idx >> 2, seg = idx & 3;
        uint32_t dofs = (uint32_t)t * ASTRIDE + (uint32_t)seg * 16;
        size_t gofs = (size_t)t * 32 + seg * 8;
        cp16(sb + AQ + dofs, qb + gofs);
        cp16(sb + AK + dofs, kb + gofs);
        cp16(sb + AV + dofs, vb + gofs);
    }
    CP_COMMIT();

    for (int i = tid; i < 225; i += 128) biasS[i] = table[i * 8 + head];
    if (tid < 64) {
        int yi = tid >> 3, xi = tid & 7;
        int h = wy * 8 + yi, w = wx * 8 + xi;
        int rh = (h < 56) ? 0 : ((h < 60) ? 1 : 2);
        int rw = (w < 56) ? 0 : ((w < 60) ? 1 : 2);
        regS[tid] = rh * 3 + rw;
    }
    CP_WAIT(0);
    __syncthreads();

    const int m0 = wid * 16;

    float accS[8][4];
#pragma unroll
    for (int i = 0; i < 8; ++i)
#pragma unroll
        for (int q = 0; q < 4; ++q) accS[i][q] = 0.f;

    const uint32_t aoff = (uint32_t)(m0 + (lane & 15)) * ASTRIDE + (uint32_t)(lane >> 4) * 16;
    const uint32_t koff = (uint32_t)(((lane >> 4) << 3) + (lane & 7)) * ASTRIDE
                        + (uint32_t)((lane >> 3) & 1) * 16;

#pragma unroll
    for (int kt = 0; kt < 2; ++kt) {
        uint32_t qf[4];
        LDSM_X4(qf, sb + AQ + aoff + kt * 32);
#pragma unroll
        for (int np = 0; np < 4; ++np) {
            uint32_t kf[4];
            LDSM_X4(kf, sb + AK + koff + (uint32_t)np * (16 * ASTRIDE) + kt * 32);
#pragma unroll
            for (int half = 0; half < 2; ++half)
                MMA_F16(accS[np * 2 + half], qf, kf + half * 2);
        }
    }

    const int r0 = m0 + (lane >> 2);
    const int r1 = r0 + 8;
    const int yi0 = r0 >> 3, xi0 = r0 & 7, rg0 = regS[r0];
    const int yi1 = r1 >> 3, xi1 = r1 & 7, rg1 = regS[r1];
#pragma unroll
    for (int nt = 0; nt < 8; ++nt) {
#pragma unroll
        for (int e = 0; e < 2; ++e) {
            int s  = nt * 8 + (lane & 3) * 2 + e;
            int ys = s >> 3, xs = s & 7;
            int rs = regS[s];
            accS[nt][e]     += biasS[(yi0 - ys + 7) * 15 + (xi0 - xs + 7)]
                             + (rs != rg0 ? -100.0f : 0.0f);
            accS[nt][2 + e] += biasS[(yi1 - ys + 7) * 15 + (xi1 - xs + 7)]
                             + (rs != rg1 ? -100.0f : 0.0f);
        }
    }

    {
        float mx0 = -1e30f, mx1 = -1e30f;
#pragma unroll
        for (int nt = 0; nt < 8; ++nt) {
            mx0 = fmaxf(mx0, fmaxf(accS[nt][0], accS[nt][1]));
            mx1 = fmaxf(mx1, fmaxf(accS[nt][2], accS[nt][3]));
        }
#pragma unroll
        for (int o = 1; o < 4; o <<= 1) {
            mx0 = fmaxf(mx0, __shfl_xor_sync(0xFFFFFFFF, mx0, o));
            mx1 = fmaxf(mx1, __shfl_xor_sync(0xFFFFFFFF, mx1, o));
        }
        float sum0 = 0.f, sum1 = 0.f;
#pragma unroll
        for (int nt = 0; nt < 8; ++nt) {
            accS[nt][0] = __expf(accS[nt][0] - mx0);
            accS[nt][1] = __expf(accS[nt][1] - mx0);
            accS[nt][2] = __expf(accS[nt][2] - mx1);
            accS[nt][3] = __expf(accS[nt][3] - mx1);
            sum0 += accS[nt][0] + accS[nt][1];
            sum1 += accS[nt][2] + accS[nt][3];
        }
#pragma unroll
        for (int o = 1; o < 4; o <<= 1) {
            sum0 += __shfl_xor_sync(0xFFFFFFFF, sum0, o);
            sum1 += __shfl_xor_sync(0xFFFFFFFF, sum1, o);
        }
        float inv0 = 1.0f / sum0, inv1 = 1.0f / sum1;
#pragma unroll
        for (int nt = 0; nt < 8; ++nt) {
            accS[nt][0] *= inv0; accS[nt][1] *= inv0;
            accS[nt][2] *= inv1; accS[nt][3] *= inv1;
        }
    }

    uint32_t pf[4][4];
#pragma unroll
    for (int kt = 0; kt < 4; ++kt) {
        pf[kt][0] = pack2h(accS[2 * kt][0],     accS[2 * kt][1]);
        pf[kt][1] = pack2h(accS[2 * kt][2],     accS[2 * kt][3]);
        pf[kt][2] = pack2h(accS[2 * kt + 1][0], accS[2 * kt + 1][1]);
        pf[kt][3] = pack2h(accS[2 * kt + 1][2], accS[2 * kt + 1][3]);
    }

    float accO[4][4];
#pragma unroll
    for (int i = 0; i < 4; ++i)
#pragma unroll
        for (int q = 0; q < 4; ++q) accO[i][q] = 0.f;

    const uint32_t vrow = (uint32_t)((lane & 7) + ((lane >> 3) & 1) * 8) * ASTRIDE
                        + (uint32_t)((lane >> 4) << 3) * 2;
#pragma unroll
    for (int kt = 0; kt < 4; ++kt) {
#pragma unroll
        for (int np = 0; np < 2; ++np) {
            uint32_t vf[4];
            LDSM_X4T(vf, sb + AV + vrow + (uint32_t)kt * (16 * ASTRIDE) + (uint32_t)np * 32);
#pragma unroll
            for (int half = 0; half < 2; ++half)
                MMA_F16(accO[np * 2 + half], pf[kt], vf + half * 2);
        }
    }

    __syncthreads();
    float* Osm = (float*)smr;
#pragma unroll
    for (int nt = 0; nt < 4; ++nt) {
        int d0 = nt * 8 + (lane & 3) * 2;
        Osm[r0 * 33 + d0]     = accO[nt][0];
        Osm[r0 * 33 + d0 + 1] = accO[nt][1];
        Osm[r1 * 33 + d0]     = accO[nt][2];
        Osm[r1 * 33 + d0 + 1] = accO[nt][3];
    }
    __syncthreads();

    size_t obase = ((size_t)b << 20) + ((size_t)head << 17);
#pragma unroll
    for (int it = 0; it < 16; ++it) {
        int idx = it * 128 + tid;
        int d = idx >> 6, t = idx & 63;
        int yi = t >> 3, xi = t & 7;
        int gh = (wy * 8 + yi + 4) & 63;
        int gw = (wx * 8 + xi + 4) & 63;
        out[obase + ((size_t)d << 12) + gh * 64 + gw] = Osm[t * 33 + d];
    }
}

// ---------------------------------------------------------------------------
extern "C" void kernel_launch(void* const* d_in, const int* in_sizes, int n_in,
                              void* d_out, int out_size)
{
    (void)in_sizes; (void)n_in; (void)out_size;
    const float* x    = (const float*)d_in[0];
    const float* qkvw = (const float*)d_in[1];
    const float* qkvb = (const float*)d_in[2];
    const float* tbl  = (const float*)d_in[3];
    float* out = (float*)d_out;

    cudaFuncSetAttribute(qkv_mma_kernel,
                         cudaFuncAttributeMaxDynamicSharedMemorySize, NSTG * STG2);

    gather_split_kernel<<<NWIN_TOT, 256>>>(x);
    transW_kernel<<<192, 256>>>(qkvw);
    qkv_mma_kernel<<<dim3(6, 1024), 256, NSTG * STG2>>>(qkvb);
    attn_kernel<<<dim3(NWIN_TOT, HEADS), 128>>>(tbl, out);
}

// round 11
// speedup vs baseline: 4.7095x; 1.0237x over previous
#include <cuda_runtime.h>
#include <cuda_bf16.h>
#include <cuda_fp16.h>
#include <cstdint>

// ---------------------------------------------------------------------------
// WindowAttention (Swin shifted-window attention).
//   B=32, DIM=256, H=W=64, WIN=8, SHIFT=4, HEADS=8, HEAD_DIM=32, N=64
// R11: GEMM K-chunk 64 (4 chunks), 3-stage mbarrier ring (no __syncthreads
//      in mainloop), 2 CTAs/SM. qkv fp16 scratch; fp16 HMMA attention.
// ---------------------------------------------------------------------------

#define NWIN_TOT   2048
#define M_TOT      131072
#define C_DIM      256
#define N3C        768
#define HEADS      8
#define HD         32
#define NTOK       64
#define SCALE      0.17677669529663687f

__device__ __half g_Ah[(size_t)M_TOT * C_DIM];
__device__ __half g_Bh[(size_t)N3C * C_DIM];
__device__ __half g_qkvh[(size_t)3 * NWIN_TOT * HEADS * NTOK * HD];

#define QKV_STRIDE ((size_t)NWIN_TOT * HEADS * NTOK * HD)

// ------------------------------ helpers -----------------------------------
__device__ __forceinline__ uint32_t smem_u32(const void* p) {
    uint32_t a;
    asm("{ .reg .u64 t; cvta.to.shared.u64 t, %1; cvt.u32.u64 %0, t; }"
        : "=r"(a) : "l"(p));
    return a;
}

__device__ __forceinline__ void cp16(uint32_t saddr, const void* g) {
    asm volatile("cp.async.cg.shared.global [%0], [%1], 16;" :: "r"(saddr), "l"(g));
}
#define CP_COMMIT()  asm volatile("cp.async.commit_group;" ::: "memory")
#define CP_WAIT(N)   asm volatile("cp.async.wait_group %0;" :: "n"(N) : "memory")

#define MBARRIER_INIT(a, cnt) \
    asm volatile("mbarrier.init.shared.b64 [%0], %1;" :: "r"((uint32_t)(a)), "r"((uint32_t)(cnt)) : "memory")
#define MBARRIER_ARRIVE(a) \
    asm volatile("mbarrier.arrive.shared.b64 _, [%0];" :: "r"((uint32_t)(a)) : "memory")
#define CP_MBAR_ARRIVE(a) \
    asm volatile("cp.async.mbarrier.arrive.noinc.shared.b64 [%0];" :: "r"((uint32_t)(a)) : "memory")

#define MBARRIER_WAIT_PARITY(a, par) do { \
    uint32_t _m = (uint32_t)(a); uint32_t _p = (uint32_t)(par); uint32_t _d; \
    asm volatile("{\n\t.reg .pred p;\n\t" \
        "mbarrier.try_wait.parity.acquire.cta.shared::cta.b64 p, [%1], %2;\n\t" \
        "selp.b32 %0, 1, 0, p;\n\t}" : "=r"(_d) : "r"(_m), "r"(_p) : "memory"); \
    if (!_d) { \
        asm volatile("{\n\t.reg .pred P1;\n\t" \
            "WL_%=:\n\t" \
            "mbarrier.try_wait.parity.acquire.cta.shared::cta.b64 P1, [%0], %1, 0x989680;\n\t" \
            "@P1 bra.uni WD_%=;\n\t" \
            "bra.uni WL_%=;\n\t" \
            "WD_%=:\n\t}" :: "r"(_m), "r"(_p) : "memory"); \
    } \
} while (0)

#define LDSM_X4(r, addr) \
    asm volatile("ldmatrix.sync.aligned.m8n8.x4.shared.b16 {%0,%1,%2,%3}, [%4];" \
        : "=r"((r)[0]), "=r"((r)[1]), "=r"((r)[2]), "=r"((r)[3]) : "r"(addr))
#define LDSM_X4T(r, addr) \
    asm volatile("ldmatrix.sync.aligned.m8n8.x4.trans.shared.b16 {%0,%1,%2,%3}, [%4];" \
        : "=r"((r)[0]), "=r"((r)[1]), "=r"((r)[2]), "=r"((r)[3]) : "r"(addr))

#define MMA_F16(d, a, b) \
    asm volatile("mma.sync.aligned.m16n8k16.row.col.f32.f16.f16.f32 " \
        "{%0,%1,%2,%3}, {%4,%5,%6,%7}, {%8,%9}, {%0,%1,%2,%3};" \
        : "+f"((d)[0]), "+f"((d)[1]), "+f"((d)[2]), "+f"((d)[3]) \
        : "r"((a)[0]), "r"((a)[1]), "r"((a)[2]), "r"((a)[3]), \
          "r"((b)[0]), "r"((b)[1]))

__device__ __forceinline__ uint32_t pack2h(float x, float y)
{
    __half2 a = __floats2half2_rn(x, y);
    return *(uint32_t*)&a;
}
__device__ __forceinline__ uint2 pack4h(float v0, float v1, float v2, float v3)
{
    uint2 r;
    r.x = pack2h(v0, v1);
    r.y = pack2h(v2, v3);
    return r;
}

// ---------------------------------------------------------------------------
// K0: gather + roll + window partition + fp32->fp16
// ---------------------------------------------------------------------------
__global__ void __launch_bounds__(256)
gather_split_kernel(const float* __restrict__ x)
{
    __shared__ float sm[64 * 65];
    const int blk = blockIdx.x;
    const int b  = blk >> 6;
    const int wy = (blk >> 3) & 7;
    const int wx = blk & 7;
    const int tid = threadIdx.x;

    uint2* dh = (uint2*)g_Ah + (size_t)blk * 4096;
    const float* xb = x + ((size_t)b << 20);

#pragma unroll 1
    for (int cc = 0; cc < 4; ++cc) {
#pragma unroll
        for (int it = 0; it < 16; ++it) {
            int idx = it * 256 + tid;
            int cl = idx >> 6;
            int t  = idx & 63;
            int i = t >> 3, j = t & 7;
            int gh = (wy * 8 + i + 4) & 63;
            int gw = (wx * 8 + j + 4) & 63;
            sm[t * 65 + cl] = xb[((size_t)(cc * 64 + cl) << 12) + gh * 64 + gw];
        }
        __syncthreads();
#pragma unroll
        for (int it = 0; it < 4; ++it) {
            int idx = it * 256 + tid;
            int t  = idx >> 4;
            int cq = idx & 15;
            const float* s = sm + t * 65 + cq * 4;
            dh[t * 64 + cc * 16 + cq] = pack4h(s[0], s[1], s[2], s[3]);
        }
        __syncthreads();
    }
}

// ---------------------------------------------------------------------------
// K0b: transpose qkv_w [K=256][N=768] -> B [N][K] fp16
// ---------------------------------------------------------------------------
__global__ void __launch_bounds__(256)
transW_kernel(const float* __restrict__ W)
{
    int g = blockIdx.x * 256 + threadIdx.x;
    int n = g >> 6;
    int k4 = (g & 63) * 4;
    float v[4];
#pragma unroll
    for (int r = 0; r < 4; ++r) v[r] = W[(size_t)(k4 + r) * N3C + n];
    ((uint2*)g_Bh)[(size_t)n * 64 + (k4 >> 2)] = pack4h(v[0], v[1], v[2], v[3]);
}

// ---------------------------------------------------------------------------
// K1: fp16 HMMA QKV GEMM, barrier-free mbarrier ring mainloop.
// grid = (6, 1024), 256 threads (8 warps 4x2). Tile 128x128, K=256 in
// 4 chunks of 64, 3-stage ring, 2 CTAs/SM.
// Row: 64 fp16 = 128B data + 16B pad = 144B stride (ldsm conflict-free).
// Stage = 2 arrays * 128 rows * 144B = 36864B; 3 stages = 110592B.
// ---------------------------------------------------------------------------
#define ROWB3 144
#define ARR3  (128 * ROWB3)
#define STG3  (2 * ARR3)
#define NSTG  3
#define NCHK  4

__global__ void __launch_bounds__(256, 2)
qkv_mma_kernel(const float* __restrict__ bias)
{
    extern __shared__ __align__(128) char dsm[];
    __shared__ __align__(16) unsigned long long s_mb[2 * NSTG];
    const uint32_t su = smem_u32(dsm);
    const uint32_t mb = smem_u32(&s_mb[0]);
#define MB_FULL(s)  (mb + (uint32_t)(s) * 16u)
#define MB_EMPTY(s) (mb + (uint32_t)(s) * 16u + 8u)

    const int tid  = threadIdx.x;
    const int lane = tid & 31;
    const int wid  = tid >> 5;
    const int wm   = wid >> 1;
    const int wn   = wid & 1;
    const int n0   = blockIdx.x * 128;
    const int m0   = blockIdx.y * 128;

    const __half* pA = g_Ah + (size_t)m0 * C_DIM;
    const __half* pB = g_Bh + (size_t)n0 * C_DIM;

    const int ldSeg = tid & 7;            // 16B segment within 128B row
    const int ldRow = tid >> 3;           // 0..31

    const uint32_t aRow = (uint32_t)(wm * 32 + (lane & 15)) * ROWB3
                        + (uint32_t)(lane >> 4) * 16;
    const uint32_t bRow = (uint32_t)(wn * 64 + ((lane >> 4) << 3) + (lane & 7)) * ROWB3
                        + (uint32_t)((lane >> 3) & 1) * 16;

    if (tid == 0) {
#pragma unroll
        for (int s = 0; s < NSTG; ++s) {
            MBARRIER_INIT(MB_FULL(s), 256);
            MBARRIER_INIT(MB_EMPTY(s), 256);
        }
    }
    __syncthreads();          // the ONLY CTA-wide barrier

    float acc[2][8][4];
#pragma unroll
    for (int i = 0; i < 2; ++i)
#pragma unroll
        for (int j = 0; j < 8; ++j)
#pragma unroll
            for (int q = 0; q < 4; ++q) acc[i][j][q] = 0.f;

    // produce chunk c into stage st (after waiting empty at phase ep)
    auto produce = [&](int c, int st, int ep) {
        MBARRIER_WAIT_PARITY(MB_EMPTY(st), ep);
        const uint32_t sb = su + (uint32_t)st * STG3;
        const int kb = c * 64 + ldSeg * 8;
#pragma unroll
        for (int p = 0; p < 4; ++p) {
            int row = p * 32 + ldRow;
            uint32_t so = (uint32_t)row * ROWB3 + (uint32_t)ldSeg * 16;
            size_t gi = (size_t)row * C_DIM + kb;
            cp16(sb + so,        pA + gi);
            cp16(sb + ARR3 + so, pB + gi);
        }
        CP_MBAR_ARRIVE(MB_FULL(st));
    };

    // prologue: chunks 0,1 (fresh empty barriers pass at phase 1)
    produce(0, 0, 1);
    produce(1, 1, 1);
    int pstage = 2, pphase = 1;
    int fstage = 0, fphase = 0;

#pragma unroll 1
    for (int c = 0; c < NCHK; ++c) {
        MBARRIER_WAIT_PARITY(MB_FULL(fstage), fphase);

        const uint32_t sb = su + (uint32_t)fstage * STG3;
        const uint32_t sA = sb;
        const uint32_t sB = sb + ARR3;

#pragma unroll
        for (int ks = 0; ks < 4; ++ks) {
            uint32_t ah[2][4];
#pragma unroll
            for (int mt = 0; mt < 2; ++mt) {
                uint32_t ao = aRow + (uint32_t)mt * (16 * ROWB3) + (uint32_t)ks * 32;
                LDSM_X4(ah[mt], sA + ao);
            }
#pragma unroll
            for (int np = 0; np < 4; ++np) {
                uint32_t bo = bRow + (uint32_t)np * (16 * ROWB3) + (uint32_t)ks * 32;
                uint32_t bh[4];
                LDSM_X4(bh, sB + bo);
#pragma unroll
                for (int half = 0; half < 2; ++half) {
                    int nt = np * 2 + half;
                    MMA_F16(acc[0][nt], ah[0], bh + half * 2);
                    MMA_F16(acc[1][nt], ah[1], bh + half * 2);
                }
            }
        }

        MBARRIER_ARRIVE(MB_EMPTY(fstage));
        if (c + 2 < NCHK) {
            produce(c + 2, pstage, pphase);
            if (++pstage == NSTG) { pstage = 0; pphase ^= 1; }
        }
        if (++fstage == NSTG) { fstage = 0; fphase ^= 1; }
    }

    // ---- epilogue: bias (+SCALE for Q), fp16 pack, scatter to g_qkvh ----
#pragma unroll
    for (int nt = 0; nt < 8; ++nt) {
        const int n = n0 + wn * 64 + nt * 8 + (lane & 3) * 2;
        const float2 bv = *(const float2*)(bias + n);
        const int which = n >> 8;
        const int head  = (n >> 5) & 7;
        const int d     = n & 31;
        const float scl = (which == 0) ? SCALE : 1.0f;
        const size_t nbase = (size_t)which * QKV_STRIDE + (size_t)head * (NTOK * HD) + d;
#pragma unroll
        for (int mt = 0; mt < 2; ++mt) {
            const int mb2 = m0 + wm * 32 + mt * 16 + (lane >> 2);
#pragma unroll
            for (int h = 0; h < 2; ++h) {
                const int m   = mb2 + h * 8;
                const int win = m >> 6;
                const int t   = m & 63;
                uint32_t pk = pack2h((acc[mt][nt][h * 2 + 0] + bv.x) * scl,
                                     (acc[mt][nt][h * 2 + 1] + bv.y) * scl);
                *(uint32_t*)(g_qkvh + nbase
                    + ((size_t)win * (HEADS * NTOK * HD) + (size_t)t * HD)) = pk;
            }
        }
    }
#undef MB_FULL
#undef MB_EMPTY
}

// ---------------------------------------------------------------------------
// K2: fp16 HMMA attention. grid = (2048, 8), 128 threads (4 warps).
// Q/K/V fp16 in smem via raw cp.async; fp32 register softmax.
// ---------------------------------------------------------------------------
#define ASTRIDE 80
#define AQ 0
#define AK 5120
#define AV 10240

__global__ void __launch_bounds__(128)
attn_kernel(const float* __restrict__ table,
            float* __restrict__ out)
{
    __shared__ __align__(16) char smr[15360];
    __shared__ float biasS[225];
    __shared__ int   regS[64];

    const int win  = blockIdx.x;
    const int head = blockIdx.y;
    const int b  = win >> 6;
    const int wy = (win >> 3) & 7;
    const int wx = win & 7;

    const int tid  = threadIdx.x;
    const int lane = tid & 31;
    const int wid  = tid >> 5;
    const uint32_t sb = smem_u32(smr);

    const __half* qb = g_qkvh + (((size_t)win * HEADS + head) << 11);
    const __half* kb = qb + QKV_STRIDE;
    const __half* vb = qb + 2 * QKV_STRIDE;

#pragma unroll
    for (int it = 0; it < 2; ++it) {
        int idx = it * 128 + tid;
        int t = idx >> 2, seg = idx & 3;
        uint32_t dofs = (uint32_t)t * ASTRIDE + (uint32_t)seg * 16;
        size_t gofs = (size_t)t * 32 + seg * 8;
        cp16(sb + AQ + dofs, qb + gofs);
        cp16(sb + AK + dofs, kb + gofs);
        cp16(sb + AV + dofs, vb + gofs);
    }
    CP_COMMIT();

    for (int i = tid; i < 225; i += 128) biasS[i] = table[i * 8 + head];
    if (tid < 64) {
        int yi = tid >> 3, xi = tid & 7;
        int h = wy * 8 + yi, w = wx * 8 + xi;
        int rh = (h < 56) ? 0 : ((h < 60) ? 1 : 2);
        int rw = (w < 56) ? 0 : ((w < 60) ? 1 : 2);
        regS[tid] = rh * 3 + rw;
    }
    CP_WAIT(0);
    __syncthreads();

    const int m0 = wid * 16;

    float accS[8][4];
#pragma unroll
    for (int i = 0; i < 8; ++i)
#pragma unroll
        for (int q = 0; q < 4; ++q) accS[i][q] = 0.f;

    const uint32_t aoff = (uint32_t)(m0 + (lane & 15)) * ASTRIDE + (uint32_t)(lane >> 4) * 16;
    const uint32_t koff = (uint32_t)(((lane >> 4) << 3) + (lane & 7)) * ASTRIDE
                        + (uint32_t)((lane >> 3) & 1) * 16;

#pragma unroll
    for (int kt = 0; kt < 2; ++kt) {
        uint32_t qf[4];
        LDSM_X4(qf, sb + AQ + aoff + kt * 32);
#pragma unroll
        for (int np = 0; np < 4; ++np) {
            uint32_t kf[4];
            LDSM_X4(kf, sb + AK + koff + (uint32_t)np * (16 * ASTRIDE) + kt * 32);
#pragma unroll
            for (int half = 0; half < 2; ++half)
                MMA_F16(accS[np * 2 + half], qf, kf + half * 2);
        }
    }

    const int r0 = m0 + (lane >> 2);
    const int r1 = r0 + 8;
    const int yi0 = r0 >> 3, xi0 = r0 & 7, rg0 = regS[r0];
    const int yi1 = r1 >> 3, xi1 = r1 & 7, rg1 = regS[r1];
#pragma unroll
    for (int nt = 0; nt < 8; ++nt) {
#pragma unroll
        for (int e = 0; e < 2; ++e) {
            int s  = nt * 8 + (lane & 3) * 2 + e;
            int ys = s >> 3, xs = s & 7;
            int rs = regS[s];
            accS[nt][e]     += biasS[(yi0 - ys + 7) * 15 + (xi0 - xs + 7)]
                             + (rs != rg0 ? -100.0f : 0.0f);
            accS[nt][2 + e] += biasS[(yi1 - ys + 7) * 15 + (xi1 - xs + 7)]
                             + (rs != rg1 ? -100.0f : 0.0f);
        }
    }

    {
        float mx0 = -1e30f, mx1 = -1e30f;
#pragma unroll
        for (int nt = 0; nt < 8; ++nt) {
            mx0 = fmaxf(mx0, fmaxf(accS[nt][0], accS[nt][1]));
            mx1 = fmaxf(mx1, fmaxf(accS[nt][2], accS[nt][3]));
        }
#pragma unroll
        for (int o = 1; o < 4; o <<= 1) {
            mx0 = fmaxf(mx0, __shfl_xor_sync(0xFFFFFFFF, mx0, o));
            mx1 = fmaxf(mx1, __shfl_xor_sync(0xFFFFFFFF, mx1, o));
        }
        float sum0 = 0.f, sum1 = 0.f;
#pragma unroll
        for (int nt = 0; nt < 8; ++nt) {
            accS[nt][0] = __expf(accS[nt][0] - mx0);
            accS[nt][1] = __expf(accS[nt][1] - mx0);
            accS[nt][2] = __expf(accS[nt][2] - mx1);
            accS[nt][3] = __expf(accS[nt][3] - mx1);
            sum0 += accS[nt][0] + accS[nt][1];
            sum1 += accS[nt][2] + accS[nt][3];
        }
#pragma unroll
        for (int o = 1; o < 4; o <<= 1) {
            sum0 += __shfl_xor_sync(0xFFFFFFFF, sum0, o);
            sum1 += __shfl_xor_sync(0xFFFFFFFF, sum1, o);
        }
        float inv0 = 1.0f / sum0, inv1 = 1.0f / sum1;
#pragma unroll
        for (int nt = 0; nt < 8; ++nt) {
            accS[nt][0] *= inv0; accS[nt][1] *= inv0;
            accS[nt][2] *= inv1; accS[nt][3] *= inv1;
        }
    }

    uint32_t pf[4][4];
#pragma unroll
    for (int kt = 0; kt < 4; ++kt) {
        pf[kt][0] = pack2h(accS[2 * kt][0],     accS[2 * kt][1]);
        pf[kt][1] = pack2h(accS[2 * kt][2],     accS[2 * kt][3]);
        pf[kt][2] = pack2h(accS[2 * kt + 1][0], accS[2 * kt + 1][1]);
        pf[kt][3] = pack2h(accS[2 * kt + 1][2], accS[2 * kt + 1][3]);
    }

    float accO[4][4];
#pragma unroll
    for (int i = 0; i < 4; ++i)
#pragma unroll
        for (int q = 0; q < 4; ++q) accO[i][q] = 0.f;

    const uint32_t vrow = (uint32_t)((lane & 7) + ((lane >> 3) & 1) * 8) * ASTRIDE
                        + (uint32_t)((lane >> 4) << 3) * 2;
#pragma unroll
    for (int kt = 0; kt < 4; ++kt) {
#pragma unroll
        for (int np = 0; np < 2; ++np) {
            uint32_t vf[4];
            LDSM_X4T(vf, sb + AV + vrow + (uint32_t)kt * (16 * ASTRIDE) + (uint32_t)np * 32);
#pragma unroll
            for (int half = 0; half < 2; ++half)
                MMA_F16(accO[np * 2 + half], pf[kt], vf + half * 2);
        }
    }

    __syncthreads();
    float* Osm = (float*)smr;
#pragma unroll
    for (int nt = 0; nt < 4; ++nt) {
        int d0 = nt * 8 + (lane & 3) * 2;
        Osm[r0 * 33 + d0]     = accO[nt][0];
        Osm[r0 * 33 + d0 + 1] = accO[nt][1];
        Osm[r1 * 33 + d0]     = accO[nt][2];
        Osm[r1 * 33 + d0 + 1] = accO[nt][3];
    }
    __syncthreads();

    size_t obase = ((size_t)b << 20) + ((size_t)head << 17);
#pragma unroll
    for (int it = 0; it < 16; ++it) {
        int idx = it * 128 + tid;
        int d = idx >> 6, t = idx & 63;
        int yi = t >> 3, xi = t & 7;
        int gh = (wy * 8 + yi + 4) & 63;
        int gw = (wx * 8 + xi + 4) & 63;
        out[obase + ((size_t)d << 12) + gh * 64 + gw] = Osm[t * 33 + d];
    }
}

// ---------------------------------------------------------------------------
extern "C" void kernel_launch(void* const* d_in, const int* in_sizes, int n_in,
                              void* d_out, int out_size)
{
    (void)in_sizes; (void)n_in; (void)out_size;
    const float* x    = (const float*)d_in[0];
    const float* qkvw = (const float*)d_in[1];
    const float* qkvb = (const float*)d_in[2];
    const float* tbl  = (const float*)d_in[3];
    float* out = (float*)d_out;

    cudaFuncSetAttribute(qkv_mma_kernel,
                         cudaFuncAttributeMaxDynamicSharedMemorySize, NSTG * STG3);

    gather_split_kernel<<<NWIN_TOT, 256>>>(x);
    transW_kernel<<<192, 256>>>(qkvw);
    qkv_mma_kernel<<<dim3(6, 1024), 256, NSTG * STG3>>>(qkvb);
    attn_kernel<<<dim3(NWIN_TOT, HEADS), 128>>>(tbl, out);
}